// round 10
// baseline (speedup 1.0000x reference)
#include <cuda_runtime.h>
#include <cuda_bf16.h>
#include <cuda_fp16.h>
#include <math.h>
#include <stdint.h>

namespace {
constexpr int Bb = 4096, Dd = 64, Cc = 16, Hh = 512, NB = 2, NS = 8;
// small kernel (128x64 tile, BK=32, 2 bufs)
constexpr int SAS = 40;
constexpr int AT = 128 * SAS;
constexpr int BT = 64 * SAS;
constexpr int SMEM_SM = (2 * AT + 2 * AT + 2 * BT + 2 * BT) * 2 + 1024;
// big kernel (128x128 tile, BK=16, 3 bufs)
constexpr int SASB = 24;
constexpr int ATB = 128 * SASB;
constexpr int SMEM_BIG = 4 * 3 * ATB * 2 + 1024;
}

// ---------------- device scratch ----------------
__device__ __align__(16) __nv_bfloat16 g_h1h[Bb * Hh], g_h1l[Bb * Hh];
__device__ __align__(16) __nv_bfloat16 g_h2h[Bb * Hh], g_h2l[Bb * Hh];
__device__ __align__(16) __nv_bfloat16 g_yinh[Bb * Dd], g_yinl[Bb * Dd];
__device__ __align__(16) float g_y[Bb * Dd], g_yacc[Bb * Dd];
__device__ __align__(16) float g_cb[NB * Bb * Hh], g_G3[NB * Bb * Hh], g_E1[NB * Bb * Hh];
__device__ __align__(16) float g_ld[Bb], g_psum[4 * Bb];
__device__ __align__(16) __nv_bfloat16 g_epsh[NB * Bb * Dd],  g_epsl[NB * Bb * Dd];
__device__ __align__(16) __half        g_W2f [NB * Hh * Hh];                           // [n][k] fp16 B2
__device__ __align__(16) __nv_bfloat16 g_W2Th[NB * Hh * Hh],  g_W2Tl[NB * Hh * Hh];   // [n][k] F2
__device__ __align__(16) __nv_bfloat16 g_W3h [NB * Hh * Dd],  g_W3l [NB * Hh * Dd];   // [512][64] G3
__device__ __align__(16) __nv_bfloat16 g_W3Th[NB * Dd * Hh],  g_W3Tl[NB * Dd * Hh];   // [64][512] F3
__device__ __align__(16) __nv_bfloat16 g_W1yTh[NB * Hh * Dd], g_W1yTl[NB * Hh * Dd];  // [512][64] F1/E1

// ---------------- helpers ----------------
__device__ __forceinline__ uint32_t sptr(const void* p) {
    return (uint32_t)__cvta_generic_to_shared(p);
}
__device__ __forceinline__ void ldm4(uint32_t a, uint32_t& r0, uint32_t& r1,
                                     uint32_t& r2, uint32_t& r3) {
    asm volatile("ldmatrix.sync.aligned.m8n8.x4.shared.b16 {%0,%1,%2,%3}, [%4];"
                 : "=r"(r0), "=r"(r1), "=r"(r2), "=r"(r3) : "r"(a));
}
__device__ __forceinline__ void mma_bf16(float* c, const uint32_t* a, uint32_t b0, uint32_t b1) {
    asm volatile("mma.sync.aligned.m16n8k16.row.col.f32.bf16.bf16.f32 "
                 "{%0,%1,%2,%3}, {%4,%5,%6,%7}, {%8,%9}, {%0,%1,%2,%3};"
                 : "+f"(c[0]), "+f"(c[1]), "+f"(c[2]), "+f"(c[3])
                 : "r"(a[0]), "r"(a[1]), "r"(a[2]), "r"(a[3]), "r"(b0), "r"(b1));
}
__device__ __forceinline__ void mma_f16(float* c, const uint32_t* a, uint32_t b0, uint32_t b1) {
    asm volatile("mma.sync.aligned.m16n8k16.row.col.f32.f16.f16.f32 "
                 "{%0,%1,%2,%3}, {%4,%5,%6,%7}, {%8,%9}, {%0,%1,%2,%3};"
                 : "+f"(c[0]), "+f"(c[1]), "+f"(c[2]), "+f"(c[3])
                 : "r"(a[0]), "r"(a[1]), "r"(a[2]), "r"(a[3]), "r"(b0), "r"(b1));
}
__device__ __forceinline__ void cp16(void* dst, const void* src) {
    asm volatile("cp.async.cg.shared.global [%0], [%1], 16;"
                 :: "r"(sptr(dst)), "l"(src));
}
#define CP_COMMIT() asm volatile("cp.async.commit_group;" ::: "memory")
#define CP_WAIT1()  asm volatile("cp.async.wait_group 1;" ::: "memory")
#define CP_WAIT0()  asm volatile("cp.async.wait_group 0;" ::: "memory")

__device__ __forceinline__ unsigned pack_split2(float v0, float v1, unsigned& lo_out) {
    __nv_bfloat16 h0 = __float2bfloat16(v0), h1 = __float2bfloat16(v1);
    __nv_bfloat16 l0 = __float2bfloat16(v0 - __bfloat162float(h0));
    __nv_bfloat16 l1 = __float2bfloat16(v1 - __bfloat162float(h1));
    lo_out = (unsigned)__bfloat16_as_ushort(l0) | ((unsigned)__bfloat16_as_ushort(l1) << 16);
    return (unsigned)__bfloat16_as_ushort(h0) | ((unsigned)__bfloat16_as_ushort(h1) << 16);
}
__device__ __forceinline__ float bf2sum(unsigned hi, unsigned lo, int half) {
    unsigned short h = (unsigned short)(half ? (hi >> 16) : hi);
    unsigned short l = (unsigned short)(half ? (lo >> 16) : lo);
    return __bfloat162float(__ushort_as_bfloat16(h)) + __bfloat162float(__ushort_as_bfloat16(l));
}
__device__ __forceinline__ float ftanh(float x) {
    const float cx = fminf(fmaxf(x, -15.f), 15.f);
    const float e = __expf(2.f * cx);
    return __fdividef(e - 1.f, e + 1.f);
}

struct P {
    const __nv_bfloat16 *Ah, *Al, *Bh, *Bl, *B2h, *B2l;
    const float *Amask;
    const __nv_bfloat16 *Mh, *Ml;
    const __half *W2f;
    const __nv_bfloat16 *F3Ah, *F3Al, *F3Bh, *F3Bl;
    float *C, *C2;
    const float *cbias, *w1t, *bias, *b3, *E1;
    const __nv_bfloat16 *h1h, *h1l;
    __nv_bfloat16 *Oh, *Ol;
    float *y, *yacc, *ld, *psum;
    int stage;
    float t, cacc, cin, foldcoef;
};

// ============ small kernel: 128x64 tile, BK=32, K=64 GEMMs ============
// MODE 0: by<8 G3 / by>=8 E1 (fp32 C)      grid (32,16)
// MODE 1: by<8 F1 (tanh epi); by==8 fold   grid (32,9)
template <int MODE>
__global__ void __launch_bounds__(256, 3) mma_k(P p) {
    extern __shared__ __align__(16) char dynsmem[];
    __nv_bfloat16* sAh = (__nv_bfloat16*)dynsmem;
    __nv_bfloat16* sAl = sAh + 2 * AT;
    __nv_bfloat16* sBh = sAl + 2 * AT;
    __nv_bfloat16* sBl = sBh + 2 * BT;

    const int tid = threadIdx.x, lane = tid & 31, wid = tid >> 5;
    const int wm = wid & 3, wn = wid >> 2;
    const int m0 = blockIdx.x * 128, by = blockIdx.y;

    if (MODE == 1 && by == 8) {   // fold rider
        if (p.foldcoef != 0.f && tid < 128) {
            const int m = m0 + tid;
            float s = 0.f;
            #pragma unroll
            for (int c = 0; c < 4; c++) s += p.psum[c * Bb + m];
            p.ld[m] += p.foldcoef * s;
        }
        return;
    }

    const __nv_bfloat16 *Ah = p.Ah, *Al = p.Al, *Bhp, *Blp;
    int n0;
    float* C0 = nullptr;
    if (MODE == 0) {
        if (by < 8) { Bhp = p.Bh; Blp = p.Bl; C0 = p.C; n0 = by * 64; }
        else        { Bhp = p.B2h; Blp = p.B2l; C0 = p.C2; n0 = (by - 8) * 64; }
    } else {
        Bhp = p.Bh; Blp = p.Bl; n0 = by * 64;
    }
    constexpr int K = 64, lda = 64, ldb = 64, NT = K / 32;

    auto issue = [&](int kt) {
        const int buf = kt & 1;
        const int k0 = kt * 32;
        #pragma unroll
        for (int c = tid; c < 1024; c += 256) {
            const int plane = c >> 9, cc = c & 511;
            const int row = cc >> 2, ku = cc & 3;
            cp16((plane ? sAl : sAh) + buf * AT + row * SAS + ku * 8,
                 (plane ? Al : Ah) + (size_t)(m0 + row) * lda + k0 + ku * 8);
        }
        #pragma unroll
        for (int c = tid; c < 512; c += 256) {
            const int plane = c >> 8, cc = c & 255;
            const int row = cc >> 2, ku = cc & 3;
            cp16((plane ? sBl : sBh) + buf * BT + row * SAS + ku * 8,
                 (plane ? Blp : Bhp) + (size_t)(n0 + row) * ldb + k0 + ku * 8);
        }
        CP_COMMIT();
    };

    const int l7 = lane & 7;
    const int aro = l7 + ((lane >> 3) & 1) * 8;
    const int aco = (lane >> 4) * 8;
    const int bro = l7 + (lane >> 4) * 8;
    const int bco = ((lane >> 3) & 1) * 8;

    float acc[2][4][4] = {};

    auto compute = [&](int buf) {
        const uint32_t bAh = sptr(sAh + buf * AT);
        const uint32_t bAl = sptr(sAl + buf * AT);
        const uint32_t bBh = sptr(sBh + buf * BT);
        const uint32_t bBl = sptr(sBl + buf * BT);
        #pragma unroll
        for (int kk = 0; kk < 2; kk++) {
            uint32_t ah[2][4], al[2][4], bh[2][4], bl[2][4];
            #pragma unroll
            for (int mt = 0; mt < 2; mt++) {
                const uint32_t off = ((wm * 32 + mt * 16 + aro) * SAS + kk * 16 + aco) * 2;
                ldm4(bAh + off, ah[mt][0], ah[mt][1], ah[mt][2], ah[mt][3]);
                ldm4(bAl + off, al[mt][0], al[mt][1], al[mt][2], al[mt][3]);
            }
            #pragma unroll
            for (int pn = 0; pn < 2; pn++) {
                const uint32_t off = ((wn * 32 + pn * 16 + bro) * SAS + kk * 16 + bco) * 2;
                ldm4(bBh + off, bh[pn][0], bh[pn][1], bh[pn][2], bh[pn][3]);
                ldm4(bBl + off, bl[pn][0], bl[pn][1], bl[pn][2], bl[pn][3]);
            }
            #pragma unroll
            for (int mt = 0; mt < 2; mt++)
                #pragma unroll
                for (int nt = 0; nt < 4; nt++) {
                    const uint32_t b0h = bh[nt >> 1][(nt & 1) * 2], b1h = bh[nt >> 1][(nt & 1) * 2 + 1];
                    const uint32_t b0l = bl[nt >> 1][(nt & 1) * 2], b1l = bl[nt >> 1][(nt & 1) * 2 + 1];
                    mma_bf16(acc[mt][nt], ah[mt], b0h, b1h);
                    mma_bf16(acc[mt][nt], ah[mt], b0l, b1l);
                    mma_bf16(acc[mt][nt], al[mt], b0h, b1h);
                }
        }
    };

    issue(0);
    for (int kt = 0; kt < NT; kt++) {
        if (kt + 1 < NT) { issue(kt + 1); CP_WAIT1(); } else { CP_WAIT0(); }
        __syncthreads();
        compute(kt & 1);
        __syncthreads();
    }

    const int g = lane >> 2, tt = lane & 3;
    #pragma unroll
    for (int mt = 0; mt < 2; mt++)
        #pragma unroll
        for (int nt = 0; nt < 4; nt++) {
            const int c = n0 + wn * 32 + nt * 8 + tt * 2;
            #pragma unroll
            for (int hr = 0; hr < 2; hr++) {
                const int r = m0 + wm * 32 + mt * 16 + g + hr * 8;
                float v0 = acc[mt][nt][hr * 2 + 0];
                float v1 = acc[mt][nt][hr * 2 + 1];
                const size_t off = (size_t)r * 512 + c;
                if (MODE == 0) {
                    *(float2*)&C0[off] = make_float2(v0, v1);
                } else {
                    const float2 cb = *(const float2*)&p.cbias[off];
                    const float2 wt = *(const float2*)&p.w1t[c];
                    v0 = ftanh(v0 + cb.x + p.t * wt.x);
                    v1 = ftanh(v1 + cb.y + p.t * wt.y);
                    unsigned lo, hi = pack_split2(v0, v1, lo);
                    ((unsigned*)p.Oh)[off >> 1] = hi;
                    ((unsigned*)p.Ol)[off >> 1] = lo;
                }
            }
        }
}

// ============ big kernel: 128x128 tile, BK=16, 3 bufs, K=512 ============
// MODE 2: F2 (tanh -> h2 planes)                      grid (32,4)
// MODE 3: by<4 B2 fp16 (masked A, logdet dot) / by==4 F3 (bf16 3-term, N=64) + RK4   grid (32,5)
template <int MODE>
__global__ void __launch_bounds__(256, 2) big_k(P p) {
    extern __shared__ __align__(16) char dynsmem[];
    __nv_bfloat16* sAh = (__nv_bfloat16*)dynsmem;
    __nv_bfloat16* sAl = sAh + 3 * ATB;
    __nv_bfloat16* sBh = sAl + 3 * ATB;
    __nv_bfloat16* sBl = sBh + 3 * ATB;
    float* red = (float*)(sBl + 3 * ATB);

    const int tid = threadIdx.x, lane = tid & 31, wid = tid >> 5;
    const int wm = wid & 3, wn = wid >> 2;
    const int m0 = blockIdx.x * 128, by = blockIdx.y;

    const bool isF3 = (MODE == 3 && by == 4);
    const bool isB2 = (MODE == 3 && !isF3);
    const int n0 = isF3 ? 0 : by * 128;

    const __nv_bfloat16 *Ah = nullptr, *Al = nullptr, *Bhp = nullptr, *Blp = nullptr;
    if (MODE == 2)   { Ah = p.Ah; Al = p.Al; Bhp = p.Bh; Blp = p.Bl; }
    else if (isF3)   { Ah = p.F3Ah; Al = p.F3Al; Bhp = p.F3Bh; Blp = p.F3Bl; }
    constexpr int NT = 32;   // K=512, BK=16

    auto issue = [&](int kt) {
        if (kt < NT) {
            const int buf = kt % 3;
            const int k0 = kt * 16;
            if (!isB2) {
                #pragma unroll
                for (int c = tid; c < 512; c += 256) {
                    const int plane = c >> 8, cc = c & 255;
                    const int row = cc >> 1, ku = cc & 1;
                    cp16((plane ? sAl : sAh) + buf * ATB + row * SASB + ku * 8,
                         (plane ? Al : Ah) + (size_t)(m0 + row) * 512 + k0 + ku * 8);
                }
                if (!isF3) {
                    #pragma unroll
                    for (int c = tid; c < 512; c += 256) {
                        const int plane = c >> 8, cc = c & 255;
                        const int row = cc >> 1, ku = cc & 1;
                        cp16((plane ? sBl : sBh) + buf * ATB + row * SASB + ku * 8,
                             (plane ? Blp : Bhp) + (size_t)(n0 + row) * 512 + k0 + ku * 8);
                    }
                } else {
                    const int plane = tid >> 7, cc = tid & 127;
                    const int row = cc >> 1, ku = cc & 1;
                    cp16((plane ? sBl : sBh) + buf * ATB + row * SASB + ku * 8,
                         (plane ? Blp : Bhp) + (size_t)row * 512 + k0 + ku * 8);
                }
            } else {
                // masked fp16 A (direct store) + fp16 W2 B (cp.async)
                const int row = tid >> 1, ku = tid & 1;
                const size_t go = (size_t)(m0 + row) * 512 + k0 + ku * 8;
                float gv[8];
                *(float4*)(gv)     = *(const float4*)(p.Amask + go);
                *(float4*)(gv + 4) = *(const float4*)(p.Amask + go + 4);
                const uint4 mh4 = *(const uint4*)(p.Mh + go);
                const uint4 ml4 = *(const uint4*)(p.Ml + go);
                const __nv_bfloat16* mh = (const __nv_bfloat16*)&mh4;
                const __nv_bfloat16* ml = (const __nv_bfloat16*)&ml4;
                __half hv[8];
                #pragma unroll
                for (int i = 0; i < 8; i++) {
                    const float h = __bfloat162float(mh[i]) + __bfloat162float(ml[i]);
                    hv[i] = __float2half_rn(gv[i] * (1.f - h * h));
                }
                *(uint4*)&sAh[buf * ATB + row * SASB + ku * 8] = *(const uint4*)hv;
                cp16(sBh + buf * ATB + row * SASB + ku * 8,
                     p.W2f + (size_t)(n0 + row) * 512 + k0 + ku * 8);
            }
        }
        CP_COMMIT();
    };

    const int l7 = lane & 7;
    const int aro = l7 + ((lane >> 3) & 1) * 8;
    const int aco = (lane >> 4) * 8;
    const int bro = l7 + (lane >> 4) * 8;
    const int bco = ((lane >> 3) & 1) * 8;

    float acc[2][8][4] = {};

    auto computeF2 = [&](int buf) {   // bf16 3-term, warp tile 32x64
        const uint32_t bAh = sptr(sAh + buf * ATB);
        const uint32_t bAl = sptr(sAl + buf * ATB);
        const uint32_t bBh = sptr(sBh + buf * ATB);
        const uint32_t bBl = sptr(sBl + buf * ATB);
        uint32_t ah[2][4], al[2][4], bh[4][4], bl[4][4];
        #pragma unroll
        for (int mt = 0; mt < 2; mt++) {
            const uint32_t off = ((wm * 32 + mt * 16 + aro) * SASB + aco) * 2;
            ldm4(bAh + off, ah[mt][0], ah[mt][1], ah[mt][2], ah[mt][3]);
            ldm4(bAl + off, al[mt][0], al[mt][1], al[mt][2], al[mt][3]);
        }
        #pragma unroll
        for (int pn = 0; pn < 4; pn++) {
            const uint32_t off = ((wn * 64 + pn * 16 + bro) * SASB + bco) * 2;
            ldm4(bBh + off, bh[pn][0], bh[pn][1], bh[pn][2], bh[pn][3]);
            ldm4(bBl + off, bl[pn][0], bl[pn][1], bl[pn][2], bl[pn][3]);
        }
        #pragma unroll
        for (int mt = 0; mt < 2; mt++)
            #pragma unroll
            for (int nt = 0; nt < 8; nt++) {
                const uint32_t b0h = bh[nt >> 1][(nt & 1) * 2], b1h = bh[nt >> 1][(nt & 1) * 2 + 1];
                const uint32_t b0l = bl[nt >> 1][(nt & 1) * 2], b1l = bl[nt >> 1][(nt & 1) * 2 + 1];
                mma_bf16(acc[mt][nt], ah[mt], b0h, b1h);
                mma_bf16(acc[mt][nt], ah[mt], b0l, b1l);
                mma_bf16(acc[mt][nt], al[mt], b0h, b1h);
            }
    };
    auto computeB2 = [&](int buf) {   // fp16 single, warp tile 32x64
        const uint32_t bAh = sptr(sAh + buf * ATB);
        const uint32_t bBh = sptr(sBh + buf * ATB);
        uint32_t ah[2][4], bh[4][4];
        #pragma unroll
        for (int mt = 0; mt < 2; mt++) {
            const uint32_t off = ((wm * 32 + mt * 16 + aro) * SASB + aco) * 2;
            ldm4(bAh + off, ah[mt][0], ah[mt][1], ah[mt][2], ah[mt][3]);
        }
        #pragma unroll
        for (int pn = 0; pn < 4; pn++) {
            const uint32_t off = ((wn * 64 + pn * 16 + bro) * SASB + bco) * 2;
            ldm4(bBh + off, bh[pn][0], bh[pn][1], bh[pn][2], bh[pn][3]);
        }
        #pragma unroll
        for (int mt = 0; mt < 2; mt++)
            #pragma unroll
            for (int nt = 0; nt < 8; nt++)
                mma_f16(acc[mt][nt], ah[mt],
                        bh[nt >> 1][(nt & 1) * 2], bh[nt >> 1][(nt & 1) * 2 + 1]);
    };
    auto computeF3 = [&](int buf) {   // bf16 3-term, warp tile 32x32 (N=64)
        const uint32_t bAh = sptr(sAh + buf * ATB);
        const uint32_t bAl = sptr(sAl + buf * ATB);
        const uint32_t bBh = sptr(sBh + buf * ATB);
        const uint32_t bBl = sptr(sBl + buf * ATB);
        uint32_t ah[2][4], al[2][4], bh[2][4], bl[2][4];
        #pragma unroll
        for (int mt = 0; mt < 2; mt++) {
            const uint32_t off = ((wm * 32 + mt * 16 + aro) * SASB + aco) * 2;
            ldm4(bAh + off, ah[mt][0], ah[mt][1], ah[mt][2], ah[mt][3]);
            ldm4(bAl + off, al[mt][0], al[mt][1], al[mt][2], al[mt][3]);
        }
        #pragma unroll
        for (int pn = 0; pn < 2; pn++) {
            const uint32_t off = ((wn * 32 + pn * 16 + bro) * SASB + bco) * 2;
            ldm4(bBh + off, bh[pn][0], bh[pn][1], bh[pn][2], bh[pn][3]);
            ldm4(bBl + off, bl[pn][0], bl[pn][1], bl[pn][2], bl[pn][3]);
        }
        #pragma unroll
        for (int mt = 0; mt < 2; mt++)
            #pragma unroll
            for (int nt = 0; nt < 4; nt++) {
                const uint32_t b0h = bh[nt >> 1][(nt & 1) * 2], b1h = bh[nt >> 1][(nt & 1) * 2 + 1];
                const uint32_t b0l = bl[nt >> 1][(nt & 1) * 2], b1l = bl[nt >> 1][(nt & 1) * 2 + 1];
                mma_bf16(acc[mt][nt], ah[mt], b0h, b1h);
                mma_bf16(acc[mt][nt], ah[mt], b0l, b1l);
                mma_bf16(acc[mt][nt], al[mt], b0h, b1h);
            }
    };

    issue(0);
    issue(1);
    for (int kt = 0; kt < NT; kt++) {
        CP_WAIT1();
        __syncthreads();
        issue(kt + 2);
        if (MODE == 2) computeF2(kt % 3);
        else if (isB2) computeB2(kt % 3);
        else computeF3(kt % 3);
    }

    // ---- epilogues ----
    const int g = lane >> 2, tt = lane & 3;

    if (MODE == 2) {   // tanh -> h2 planes
        #pragma unroll
        for (int mt = 0; mt < 2; mt++)
            #pragma unroll
            for (int nt = 0; nt < 8; nt++) {
                const int c = n0 + wn * 64 + nt * 8 + tt * 2;
                const float2 bi = *(const float2*)&p.bias[c];
                #pragma unroll
                for (int hr = 0; hr < 2; hr++) {
                    const int r = m0 + wm * 32 + mt * 16 + g + hr * 8;
                    const size_t off = (size_t)r * 512 + c;
                    const float v0 = ftanh(acc[mt][nt][hr * 2 + 0] + bi.x);
                    const float v1 = ftanh(acc[mt][nt][hr * 2 + 1] + bi.y);
                    unsigned lo, hi = pack_split2(v0, v1, lo);
                    ((unsigned*)p.Oh)[off >> 1] = hi;
                    ((unsigned*)p.Ol)[off >> 1] = lo;
                }
            }
        return;
    }

    if (isB2) {   // logdet dot -> psum[by]
        float s[4] = {0.f, 0.f, 0.f, 0.f};
        #pragma unroll
        for (int mt = 0; mt < 2; mt++)
            #pragma unroll
            for (int nt = 0; nt < 8; nt++) {
                const int c = n0 + wn * 64 + nt * 8 + tt * 2;
                #pragma unroll
                for (int hr = 0; hr < 2; hr++) {
                    const int r = m0 + wm * 32 + mt * 16 + g + hr * 8;
                    const size_t off = (size_t)r * 512 + c;
                    const unsigned hh = *(const unsigned*)&p.h1h[off];
                    const unsigned hl = *(const unsigned*)&p.h1l[off];
                    const float2 e = *(const float2*)&p.E1[off];
                    const float h0 = bf2sum(hh, hl, 0), h1v = bf2sum(hh, hl, 1);
                    s[mt * 2 + hr] += acc[mt][nt][hr * 2 + 0] * (1.f - h0 * h0) * e.x
                                    + acc[mt][nt][hr * 2 + 1] * (1.f - h1v * h1v) * e.y;
                }
            }
        #pragma unroll
        for (int i = 0; i < 4; i++) {
            s[i] += __shfl_xor_sync(0xffffffffu, s[i], 1);
            s[i] += __shfl_xor_sync(0xffffffffu, s[i], 2);
        }
        __syncthreads();
        if (tt == 0) {
            #pragma unroll
            for (int mt = 0; mt < 2; mt++)
                #pragma unroll
                for (int hr = 0; hr < 2; hr++)
                    red[(wm * 32 + mt * 16 + g + hr * 8) * 2 + wn] = s[mt * 2 + hr];
        }
        __syncthreads();
        if (tid < 128)
            p.psum[(size_t)by * Bb + m0 + tid] = red[tid * 2] + red[tid * 2 + 1];
        return;
    }

    // F3 + RK4
    {
        unsigned* yinhU = (unsigned*)p.Oh;
        unsigned* yinlU = (unsigned*)p.Ol;
        #pragma unroll
        for (int mt = 0; mt < 2; mt++)
            #pragma unroll
            for (int nt = 0; nt < 4; nt++) {
                const int c = wn * 32 + nt * 8 + tt * 2;
                const float2 b3v = *(const float2*)&p.b3[c];
                #pragma unroll
                for (int hr = 0; hr < 2; hr++) {
                    const int r = m0 + wm * 32 + mt * 16 + g + hr * 8;
                    const size_t idx = (size_t)r * 64 + c;
                    const float kv0 = acc[mt][nt][hr * 2 + 0] + b3v.x;
                    const float kv1 = acc[mt][nt][hr * 2 + 1] + b3v.y;
                    const float2 base = (p.stage == 1) ? *(const float2*)&p.y[idx]
                                                       : *(const float2*)&p.yacc[idx];
                    const float ya0 = base.x + p.cacc * kv0;
                    const float ya1 = base.y + p.cacc * kv1;
                    float yi0, yi1;
                    if (p.stage == 4) {
                        *(float2*)&p.y[idx] = make_float2(ya0, ya1);
                        yi0 = ya0; yi1 = ya1;
                    } else {
                        *(float2*)&p.yacc[idx] = make_float2(ya0, ya1);
                        const float2 yv = *(const float2*)&p.y[idx];
                        yi0 = yv.x + p.cin * kv0;
                        yi1 = yv.y + p.cin * kv1;
                    }
                    unsigned lo, hi = pack_split2(yi0, yi1, lo);
                    yinhU[idx >> 1] = hi;
                    yinlU[idx >> 1] = lo;
                }
            }
    }
}

// ---------------- aux kernels ----------------
__device__ __forceinline__ void wsplit(float v, __nv_bfloat16* h, __nv_bfloat16* l, size_t i) {
    const __nv_bfloat16 hv = __float2bfloat16(v);
    h[i] = hv;
    l[i] = __float2bfloat16(v - __bfloat162float(hv));
}
__global__ void prep_k(const float* __restrict__ eps, const float* __restrict__ W2,
                       const float* __restrict__ W3, const float* __restrict__ W1,
                       __nv_bfloat16* eph, __nv_bfloat16* epl,
                       __half* w2f,
                       __nv_bfloat16* w3h, __nv_bfloat16* w3l,
                       __nv_bfloat16* w2th, __nv_bfloat16* w2tl,
                       __nv_bfloat16* w1yth, __nv_bfloat16* w1ytl,
                       __nv_bfloat16* w3th, __nv_bfloat16* w3tl) {
    int i = blockIdx.x * 256 + threadIdx.x;
    if (i < Bb * Dd) { wsplit(eps[i], eph, epl, i); return; }
    i -= Bb * Dd;
    if (i < Hh * Hh) { w2f[i] = __float2half_rn(W2[i]); return; }
    i -= Hh * Hh;
    if (i < Hh * Dd) { wsplit(W3[i], w3h, w3l, i); return; }
    i -= Hh * Dd;
    if (i < Hh * Hh) {
        const int r = i / Hh, c = i % Hh;
        wsplit(W2[i], w2th, w2tl, (size_t)c * Hh + r);
        return;
    }
    i -= Hh * Hh;
    if (i < Dd * Hh) {
        const int r = i / Hh, c = i % Hh;
        wsplit(W1[i], w1yth, w1ytl, (size_t)c * Dd + r);
        return;
    }
    i -= Dd * Hh;
    if (i < Hh * Dd) {
        const int r = i / Dd, c = i % Dd;
        wsplit(W3[i], w3th, w3tl, (size_t)c * Hh + r);
    }
}
__global__ void cbias_k(const float* __restrict__ cond, const float* __restrict__ W1c,
                        const float* __restrict__ b1, float* __restrict__ cb) {
    const int m = blockIdx.x;
    const int n = threadIdx.x * 4;
    float4 acc = *(const float4*)(b1 + n);
    #pragma unroll
    for (int k = 0; k < Cc; k++) {
        const float c = cond[m * Cc + k];
        const float4 w = *(const float4*)(W1c + (size_t)k * Hh + n);
        acc.x = fmaf(c, w.x, acc.x); acc.y = fmaf(c, w.y, acc.y);
        acc.z = fmaf(c, w.z, acc.z); acc.w = fmaf(c, w.w, acc.w);
    }
    *(float4*)(cb + (size_t)m * Hh + n) = acc;
}
__global__ void init_k(const float* __restrict__ x, float* __restrict__ y,
                       __nv_bfloat16* __restrict__ yinh, __nv_bfloat16* __restrict__ yinl,
                       float* __restrict__ ld) {
    const int i = blockIdx.x * blockDim.x + threadIdx.x;
    if (i < Bb * Dd) {
        const float v = x[i];
        y[i] = v;
        wsplit(v, yinh, yinl, i);
    }
    if (i < Bb) ld[i] = 0.f;
}
__global__ void out_k(const float* __restrict__ y, const float* __restrict__ ld,
                      const float* __restrict__ psum, float coef, float* __restrict__ out) {
    const int i = blockIdx.x * blockDim.x + threadIdx.x;
    if (i >= Bb * (Dd + 1)) return;
    const int m = i / (Dd + 1), c = i % (Dd + 1);
    if (c < Dd) {
        out[i] = y[(size_t)m * Dd + c];
    } else {
        float s = 0.f;
        #pragma unroll
        for (int c2 = 0; c2 < 4; c2++) s += psum[c2 * Bb + m];
        out[i] = ld[m] + coef * s;
    }
}

// ---------------- host ----------------
extern "C" void kernel_launch(void* const* d_in, const int* in_sizes, int n_in,
                              void* d_out, int out_size) {
    const float* x    = (const float*)d_in[0];
    const float* cond = (const float*)d_in[1];
    const float* eps  = (const float*)d_in[2];
    const float* W1   = (const float*)d_in[3];
    const float* b1   = (const float*)d_in[4];
    const float* W2   = (const float*)d_in[5];
    const float* b2   = (const float*)d_in[6];
    const float* W3   = (const float*)d_in[7];
    const float* b3   = (const float*)d_in[8];
    float* out = (float*)d_out;

    cudaFuncSetAttribute(mma_k<0>, cudaFuncAttributeMaxDynamicSharedMemorySize, SMEM_SM);
    cudaFuncSetAttribute(mma_k<1>, cudaFuncAttributeMaxDynamicSharedMemorySize, SMEM_SM);
    cudaFuncSetAttribute(big_k<2>, cudaFuncAttributeMaxDynamicSharedMemorySize, SMEM_BIG);
    cudaFuncSetAttribute(big_k<3>, cudaFuncAttributeMaxDynamicSharedMemorySize, SMEM_BIG);

    #define SYM(T, v, s) T* v; { void* _p; cudaGetSymbolAddress(&_p, s); v = (T*)_p; }
    SYM(float, y, g_y) SYM(float, yacc, g_yacc) SYM(float, cb, g_cb)
    SYM(float, G3, g_G3) SYM(float, E1, g_E1) SYM(float, ld, g_ld) SYM(float, psum, g_psum)
    SYM(__nv_bfloat16, h1h, g_h1h) SYM(__nv_bfloat16, h1l, g_h1l)
    SYM(__nv_bfloat16, h2h, g_h2h) SYM(__nv_bfloat16, h2l, g_h2l)
    SYM(__nv_bfloat16, yinh, g_yinh) SYM(__nv_bfloat16, yinl, g_yinl)
    SYM(__nv_bfloat16, epsh, g_epsh) SYM(__nv_bfloat16, epsl, g_epsl)
    SYM(__half, W2f, g_W2f)
    SYM(__nv_bfloat16, W2Th, g_W2Th) SYM(__nv_bfloat16, W2Tl, g_W2Tl)
    SYM(__nv_bfloat16, W3h, g_W3h) SYM(__nv_bfloat16, W3l, g_W3l)
    SYM(__nv_bfloat16, W3Th, g_W3Th) SYM(__nv_bfloat16, W3Tl, g_W3Tl)
    SYM(__nv_bfloat16, W1yTh, g_W1yTh) SYM(__nv_bfloat16, W1yTl, g_W1yTl)
    #undef SYM

    init_k<<<(Bb * Dd + 255) / 256, 256>>>(x, y, yinh, yinl, ld);

    constexpr int PREP_N = Bb * Dd + Hh * Hh + Hh * Dd + Hh * Hh + Dd * Hh + Hh * Dd;
    const float dt = 1.0f / NS;
    float prev_cl = 0.f;

    for (int ib = 0; ib < NB; ib++) {
        const float* W1b  = W1 + (size_t)ib * (Dd + Cc + 1) * Hh;
        const float* b1b  = b1 + (size_t)ib * Hh;
        const float* W2b  = W2 + (size_t)ib * Hh * Hh;
        const float* b2b  = b2 + (size_t)ib * Hh;
        const float* W3b  = W3 + (size_t)ib * Hh * Dd;
        const float* b3b  = b3 + (size_t)ib * Dd;
        const float* epsb = eps + (size_t)ib * Bb * Dd;
        float* cbb = cb + (size_t)ib * Bb * Hh;
        float* G3b = G3 + (size_t)ib * Bb * Hh;
        float* E1b = E1 + (size_t)ib * Bb * Hh;
        __nv_bfloat16 *eph = epsh + (size_t)ib * Bb * Dd, *epl = epsl + (size_t)ib * Bb * Dd;
        __half* w2f = W2f + (size_t)ib * Hh * Hh;
        __nv_bfloat16 *w2th = W2Th + (size_t)ib * Hh * Hh, *w2tl = W2Tl + (size_t)ib * Hh * Hh;
        __nv_bfloat16 *w3h = W3h + (size_t)ib * Hh * Dd, *w3l = W3l + (size_t)ib * Hh * Dd;
        __nv_bfloat16 *w3th = W3Th + (size_t)ib * Dd * Hh, *w3tl = W3Tl + (size_t)ib * Dd * Hh;
        __nv_bfloat16 *w1yth = W1yTh + (size_t)ib * Hh * Dd, *w1ytl = W1yTl + (size_t)ib * Hh * Dd;

        prep_k<<<(PREP_N + 255) / 256, 256>>>(epsb, W2b, W3b, W1b,
            eph, epl, w2f, w3h, w3l, w2th, w2tl, w1yth, w1ytl, w3th, w3tl);
        cbias_k<<<Bb, 128>>>(cond, W1b + (size_t)Dd * Hh, b1b, cbb);

        {   // merged G3 (by<8) + E1 (by>=8)
            P p{}; p.Ah = eph; p.Al = epl;
            p.Bh = w3h; p.Bl = w3l; p.C = G3b;
            p.B2h = w1yth; p.B2l = w1ytl; p.C2 = E1b;
            mma_k<0><<<dim3(32, 16), 256, SMEM_SM>>>(p);
        }

        for (int is = 0; is < NS; is++) {
            const float tbase = is * dt;
            for (int st = 1; st <= 4; st++) {
                const float t = tbase + (st == 1 ? 0.f : (st == 4 ? dt : 0.5f * dt));
                const float cacc = (st == 1 || st == 4) ? dt / 6.f : dt / 3.f;
                const float cin  = (st == 3) ? dt : 0.5f * dt;

                {   // F1 + fold rider
                    P p{}; p.Ah = yinh; p.Al = yinl; p.Bh = w1yth; p.Bl = w1ytl;
                    p.cbias = cbb; p.w1t = W1b + (size_t)(Dd + Cc) * Hh; p.t = t;
                    p.Oh = h1h; p.Ol = h1l;
                    p.foldcoef = prev_cl; p.ld = ld; p.psum = psum;
                    mma_k<1><<<dim3(32, 9), 256, SMEM_SM>>>(p);
                }
                {   // F2 (big tile)
                    P p{}; p.Ah = h1h; p.Al = h1l; p.Bh = w2th; p.Bl = w2tl;
                    p.bias = b2b; p.Oh = h2h; p.Ol = h2l;
                    big_k<2><<<dim3(32, 4), 256, SMEM_BIG>>>(p);
                }
                {   // FUSED big: B2 fp16 + logdet (by<4), F3 + RK4 (by==4)
                    P p{};
                    p.Amask = G3b; p.Mh = h2h; p.Ml = h2l; p.W2f = w2f;
                    p.F3Ah = h2h; p.F3Al = h2l; p.F3Bh = w3th; p.F3Bl = w3tl;
                    p.h1h = h1h; p.h1l = h1l; p.E1 = E1b; p.psum = psum;
                    p.b3 = b3b; p.y = y; p.yacc = yacc; p.Oh = yinh; p.Ol = yinl;
                    p.stage = st; p.cacc = cacc; p.cin = cin;
                    big_k<3><<<dim3(32, 5), 256, SMEM_BIG>>>(p);
                }
                prev_cl = cacc;
            }
        }
    }

    out_k<<<(Bb * (Dd + 1) + 255) / 256, 256>>>(y, ld, psum, prev_cl, out);
}

// round 11
// speedup vs baseline: 1.3488x; 1.3488x over previous
#include <cuda_runtime.h>
#include <cuda_bf16.h>
#include <cuda_fp16.h>
#include <math.h>
#include <stdint.h>

namespace {
constexpr int Bb = 4096, Dd = 64, Cc = 16, Hh = 512, NB = 2, NS = 8;
constexpr int SAS = 40;               // smem row stride in halves (80B)
constexpr int AT = 128 * SAS;         // A halves per buffer
constexpr int BT = 64 * SAS;          // B halves per buffer
constexpr int SMEM_SM = (2 * AT + 2 * AT + 2 * BT) * 2 + 1024;   // A 2 planes, B 1 plane
}

// ---------------- device scratch ----------------
__device__ __align__(16) __half g_h1h[Bb * Hh], g_h1l[Bb * Hh];
__device__ __align__(16) __half g_h2h[Bb * Hh], g_h2l[Bb * Hh];
__device__ __align__(16) __half g_yinh[Bb * Dd], g_yinl[Bb * Dd];
__device__ __align__(16) float g_y[Bb * Dd], g_yacc[Bb * Dd];
__device__ __align__(16) float g_cb[NB * Bb * Hh], g_G3[NB * Bb * Hh], g_E1[NB * Bb * Hh];
__device__ __align__(16) float g_ld[Bb], g_psum[8 * Bb];
__device__ __align__(16) __half g_epsh[NB * Bb * Dd], g_epsl[NB * Bb * Dd];
__device__ __align__(16) __half g_W2f  [NB * Hh * Hh];   // [n][k] B2
__device__ __align__(16) __half g_W2Tf [NB * Hh * Hh];   // [n][k] F2
__device__ __align__(16) __half g_W3f  [NB * Hh * Dd];   // [512][64] G3
__device__ __align__(16) __half g_W3Tf [NB * Dd * Hh];   // [64][512] F3
__device__ __align__(16) __half g_W1yTf[NB * Hh * Dd];   // [512][64] F1/E1

// ---------------- helpers ----------------
__device__ __forceinline__ uint32_t sptr(const void* p) {
    return (uint32_t)__cvta_generic_to_shared(p);
}
__device__ __forceinline__ void ldm4(uint32_t a, uint32_t& r0, uint32_t& r1,
                                     uint32_t& r2, uint32_t& r3) {
    asm volatile("ldmatrix.sync.aligned.m8n8.x4.shared.b16 {%0,%1,%2,%3}, [%4];"
                 : "=r"(r0), "=r"(r1), "=r"(r2), "=r"(r3) : "r"(a));
}
__device__ __forceinline__ void mma_f16(float* c, const uint32_t* a, uint32_t b0, uint32_t b1) {
    asm volatile("mma.sync.aligned.m16n8k16.row.col.f32.f16.f16.f32 "
                 "{%0,%1,%2,%3}, {%4,%5,%6,%7}, {%8,%9}, {%0,%1,%2,%3};"
                 : "+f"(c[0]), "+f"(c[1]), "+f"(c[2]), "+f"(c[3])
                 : "r"(a[0]), "r"(a[1]), "r"(a[2]), "r"(a[3]), "r"(b0), "r"(b1));
}
__device__ __forceinline__ void cp16(void* dst, const void* src) {
    asm volatile("cp.async.cg.shared.global [%0], [%1], 16;"
                 :: "r"(sptr(dst)), "l"(src));
}
#define CP_COMMIT() asm volatile("cp.async.commit_group;" ::: "memory")
#define CP_WAIT1()  asm volatile("cp.async.wait_group 1;" ::: "memory")
#define CP_WAIT0()  asm volatile("cp.async.wait_group 0;" ::: "memory")

// split fp32 -> two fp16 planes (hi + lo, nearly exact)
__device__ __forceinline__ unsigned pack_h2(float v0, float v1, unsigned& lo_out) {
    __half h0 = __float2half_rn(v0), h1 = __float2half_rn(v1);
    __half l0 = __float2half_rn(v0 - __half2float(h0));
    __half l1 = __float2half_rn(v1 - __half2float(h1));
    lo_out = (unsigned)__half_as_ushort(l0) | ((unsigned)__half_as_ushort(l1) << 16);
    return (unsigned)__half_as_ushort(h0) | ((unsigned)__half_as_ushort(h1) << 16);
}
__device__ __forceinline__ float hsum(unsigned hi, unsigned lo, int half) {
    unsigned short h = (unsigned short)(half ? (hi >> 16) : hi);
    unsigned short l = (unsigned short)(half ? (lo >> 16) : lo);
    return __half2float(__ushort_as_half(h)) + __half2float(__ushort_as_half(l));
}
__device__ __forceinline__ float ftanh(float x) {
    const float cx = fminf(fmaxf(x, -15.f), 15.f);
    const float e = __expf(2.f * cx);
    return __fdividef(e - 1.f, e + 1.f);
}

struct P {
    const __half *Ah, *Al;          // activation planes
    const __half *Bf, *B2f;         // single fp16 weight planes
    const float *Amask;             // G3 for B2 mask
    const __half *Mh, *Ml;          // h2 planes for mask
    const __half *W2f;              // fp16 W2 [n][k] for B2
    const __half *F3Ah, *F3Al, *F3Bf;
    float *C, *C2;
    const float *cbias, *w1t, *bias, *b3, *E1;
    const __half *h1h, *h1l;
    __half *Oh, *Ol;
    float *y, *yacc, *ld, *psum;
    int stage;
    float t, cacc, cin, foldcoef;
};

// 128x64 CTA tile, 256 threads (8 warps: wm=wid&3, wn=wid>>2).
// MODE 0: by<8 G3 / by>=8 E1 (K=64, fp32 C)                  grid (32,16)
// MODE 1: by<8 F1 (K=64, tanh epi); by==8 fold rider          grid (32,9)
// MODE 2: F2 (K=512, tanh -> h2 planes)                       grid (32,8)
// MODE 3: by<8 B2 (K=512, masked fp16 A, logdet dot) / by==8 F3 + RK4   grid (32,9)
template <int MODE>
__global__ void __launch_bounds__(256, 3) mma_k(P p) {
    extern __shared__ __align__(16) char dynsmem[];
    __half* sAh = (__half*)dynsmem;
    __half* sAl = sAh + 2 * AT;
    __half* sBh = sAl + 2 * AT;
    float* red = (float*)(sBh + 2 * BT);

    const int tid = threadIdx.x, lane = tid & 31, wid = tid >> 5;
    const int wm = wid & 3, wn = wid >> 2;
    const int m0 = blockIdx.x * 128, by = blockIdx.y;

    if (MODE == 1 && by == 8) {   // fold rider
        if (p.foldcoef != 0.f && tid < 128) {
            const int m = m0 + tid;
            float s = 0.f;
            #pragma unroll
            for (int c = 0; c < 8; c++) s += p.psum[c * Bb + m];
            p.ld[m] += p.foldcoef * s;
        }
        return;
    }

    const bool isF3 = (MODE == 3 && by == 8);
    const bool maskA = (MODE == 3) && !isF3;   // B2: single fp16 A

    const __half *Ah, *Al, *Bfp;
    int lda, ldb, K, n0;
    float* C0 = nullptr;
    if (MODE == 0) {
        K = 64; lda = 64; ldb = 64;
        Ah = p.Ah; Al = p.Al;
        if (by < 8) { Bfp = p.Bf; C0 = p.C; n0 = by * 64; }
        else        { Bfp = p.B2f; C0 = p.C2; n0 = (by - 8) * 64; }
    } else if (MODE == 1) {
        K = 64; lda = 64; ldb = 64; n0 = by * 64;
        Ah = p.Ah; Al = p.Al; Bfp = p.Bf;
    } else if (MODE == 2) {
        K = 512; lda = 512; ldb = 512; n0 = by * 64;
        Ah = p.Ah; Al = p.Al; Bfp = p.Bf;
    } else if (!isF3) {
        K = 512; lda = 512; ldb = 512; n0 = by * 64;
        Ah = nullptr; Al = nullptr; Bfp = p.W2f;
    } else {
        K = 512; lda = 512; ldb = 512; n0 = 0;
        Ah = p.F3Ah; Al = p.F3Al; Bfp = p.F3Bf;
    }
    const int NT = K / 32;

    auto issue = [&](int kt) {
        const int buf = kt & 1;
        const int k0 = kt * 32;
        if (!maskA) {
            #pragma unroll
            for (int c = tid; c < 1024; c += 256) {
                const int plane = c >> 9, cc = c & 511;
                const int row = cc >> 2, ku = cc & 3;
                cp16((plane ? sAl : sAh) + buf * AT + row * SAS + ku * 8,
                     (plane ? Al : Ah) + (size_t)(m0 + row) * lda + k0 + ku * 8);
            }
        } else {
            #pragma unroll
            for (int c = tid; c < 512; c += 256) {
                const int row = c >> 2, ku = c & 3;
                const size_t go = (size_t)(m0 + row) * 512 + k0 + ku * 8;
                float g[8];
                *(float4*)(g)     = *(const float4*)(p.Amask + go);
                *(float4*)(g + 4) = *(const float4*)(p.Amask + go + 4);
                const uint4 mh4 = *(const uint4*)(p.Mh + go);
                const uint4 ml4 = *(const uint4*)(p.Ml + go);
                const __half* mh = (const __half*)&mh4;
                const __half* ml = (const __half*)&ml4;
                __half hv[8];
                #pragma unroll
                for (int i = 0; i < 8; i++) {
                    const float h = __half2float(mh[i]) + __half2float(ml[i]);
                    hv[i] = __float2half_rn(g[i] * (1.f - h * h));
                }
                *(uint4*)&sAh[buf * AT + row * SAS + ku * 8] = *(const uint4*)hv;
            }
        }
        {   // B single plane: 64 rows x 32k = 256 chunks, one per thread
            const int row = tid >> 2, ku = tid & 3;
            cp16(sBh + buf * BT + row * SAS + ku * 8,
                 Bfp + (size_t)(n0 + row) * ldb + k0 + ku * 8);
        }
        CP_COMMIT();
    };

    const int l7 = lane & 7;
    const int aro = l7 + ((lane >> 3) & 1) * 8;
    const int aco = (lane >> 4) * 8;
    const int bro = l7 + (lane >> 4) * 8;
    const int bco = ((lane >> 3) & 1) * 8;

    float acc[2][4][4] = {};

    auto compute = [&](int buf) {
        const uint32_t bAh = sptr(sAh + buf * AT);
        const uint32_t bAl = sptr(sAl + buf * AT);
        const uint32_t bBh = sptr(sBh + buf * BT);
        #pragma unroll
        for (int kk = 0; kk < 2; kk++) {
            uint32_t ah[2][4], al[2][4], bh[2][4];
            #pragma unroll
            for (int mt = 0; mt < 2; mt++) {
                const uint32_t off = ((wm * 32 + mt * 16 + aro) * SAS + kk * 16 + aco) * 2;
                ldm4(bAh + off, ah[mt][0], ah[mt][1], ah[mt][2], ah[mt][3]);
                if (!maskA) ldm4(bAl + off, al[mt][0], al[mt][1], al[mt][2], al[mt][3]);
            }
            #pragma unroll
            for (int pn = 0; pn < 2; pn++) {
                const uint32_t off = ((wn * 32 + pn * 16 + bro) * SAS + kk * 16 + bco) * 2;
                ldm4(bBh + off, bh[pn][0], bh[pn][1], bh[pn][2], bh[pn][3]);
            }
            #pragma unroll
            for (int mt = 0; mt < 2; mt++)
                #pragma unroll
                for (int nt = 0; nt < 4; nt++) {
                    const uint32_t b0 = bh[nt >> 1][(nt & 1) * 2], b1 = bh[nt >> 1][(nt & 1) * 2 + 1];
                    mma_f16(acc[mt][nt], ah[mt], b0, b1);
                    if (!maskA) mma_f16(acc[mt][nt], al[mt], b0, b1);
                }
        }
    };

    issue(0);
    for (int kt = 0; kt < NT; kt++) {
        if (kt + 1 < NT) { issue(kt + 1); CP_WAIT1(); } else { CP_WAIT0(); }
        __syncthreads();
        compute(kt & 1);
        __syncthreads();
    }

    // ---- epilogues ----
    const int g = lane >> 2, tt = lane & 3;

    if (MODE == 3 && !isF3) {   // B2 logdet dot
        float s[4] = {0.f, 0.f, 0.f, 0.f};
        #pragma unroll
        for (int mt = 0; mt < 2; mt++)
            #pragma unroll
            for (int nt = 0; nt < 4; nt++) {
                const int c = n0 + wn * 32 + nt * 8 + tt * 2;
                #pragma unroll
                for (int hr = 0; hr < 2; hr++) {
                    const int r = m0 + wm * 32 + mt * 16 + g + hr * 8;
                    const size_t off = (size_t)r * 512 + c;
                    const unsigned hh = *(const unsigned*)&p.h1h[off];
                    const unsigned hl = *(const unsigned*)&p.h1l[off];
                    const float2 e = *(const float2*)&p.E1[off];
                    const float h0 = hsum(hh, hl, 0), h1v = hsum(hh, hl, 1);
                    s[mt * 2 + hr] += acc[mt][nt][hr * 2 + 0] * (1.f - h0 * h0) * e.x
                                    + acc[mt][nt][hr * 2 + 1] * (1.f - h1v * h1v) * e.y;
                }
            }
        #pragma unroll
        for (int i = 0; i < 4; i++) {
            s[i] += __shfl_xor_sync(0xffffffffu, s[i], 1);
            s[i] += __shfl_xor_sync(0xffffffffu, s[i], 2);
        }
        if (tt == 0) {
            #pragma unroll
            for (int mt = 0; mt < 2; mt++)
                #pragma unroll
                for (int hr = 0; hr < 2; hr++)
                    red[(wm * 32 + mt * 16 + g + hr * 8) * 2 + wn] = s[mt * 2 + hr];
        }
        __syncthreads();
        if (tid < 128)
            p.psum[(size_t)by * Bb + m0 + tid] = red[tid * 2] + red[tid * 2 + 1];
        return;
    }

    if (isF3) {   // F3 + RK4
        unsigned* yinhU = (unsigned*)p.Oh;
        unsigned* yinlU = (unsigned*)p.Ol;
        #pragma unroll
        for (int mt = 0; mt < 2; mt++)
            #pragma unroll
            for (int nt = 0; nt < 4; nt++) {
                const int c = wn * 32 + nt * 8 + tt * 2;
                const float2 b3v = *(const float2*)&p.b3[c];
                #pragma unroll
                for (int hr = 0; hr < 2; hr++) {
                    const int r = m0 + wm * 32 + mt * 16 + g + hr * 8;
                    const size_t idx = (size_t)r * 64 + c;
                    const float kv0 = acc[mt][nt][hr * 2 + 0] + b3v.x;
                    const float kv1 = acc[mt][nt][hr * 2 + 1] + b3v.y;
                    const float2 base = (p.stage == 1) ? *(const float2*)&p.y[idx]
                                                       : *(const float2*)&p.yacc[idx];
                    const float ya0 = base.x + p.cacc * kv0;
                    const float ya1 = base.y + p.cacc * kv1;
                    float yi0, yi1;
                    if (p.stage == 4) {
                        *(float2*)&p.y[idx] = make_float2(ya0, ya1);
                        yi0 = ya0; yi1 = ya1;
                    } else {
                        *(float2*)&p.yacc[idx] = make_float2(ya0, ya1);
                        const float2 yv = *(const float2*)&p.y[idx];
                        yi0 = yv.x + p.cin * kv0;
                        yi1 = yv.y + p.cin * kv1;
                    }
                    unsigned lo, hi = pack_h2(yi0, yi1, lo);
                    yinhU[idx >> 1] = hi;
                    yinlU[idx >> 1] = lo;
                }
            }
        return;
    }

    // MODE 0/1/2 fragment epilogues
    #pragma unroll
    for (int mt = 0; mt < 2; mt++)
        #pragma unroll
        for (int nt = 0; nt < 4; nt++) {
            const int c = n0 + wn * 32 + nt * 8 + tt * 2;
            #pragma unroll
            for (int hr = 0; hr < 2; hr++) {
                const int r = m0 + wm * 32 + mt * 16 + g + hr * 8;
                float v0 = acc[mt][nt][hr * 2 + 0];
                float v1 = acc[mt][nt][hr * 2 + 1];
                const size_t off = (size_t)r * 512 + c;
                if (MODE == 0) {
                    *(float2*)&C0[off] = make_float2(v0, v1);
                } else if (MODE == 1) {
                    const float2 cb = *(const float2*)&p.cbias[off];
                    const float2 wt = *(const float2*)&p.w1t[c];
                    v0 = ftanh(v0 + cb.x + p.t * wt.x);
                    v1 = ftanh(v1 + cb.y + p.t * wt.y);
                    unsigned lo, hi = pack_h2(v0, v1, lo);
                    ((unsigned*)p.Oh)[off >> 1] = hi;
                    ((unsigned*)p.Ol)[off >> 1] = lo;
                } else {
                    const float2 bi = *(const float2*)&p.bias[c];
                    v0 = ftanh(v0 + bi.x);
                    v1 = ftanh(v1 + bi.y);
                    unsigned lo, hi = pack_h2(v0, v1, lo);
                    ((unsigned*)p.Oh)[off >> 1] = hi;
                    ((unsigned*)p.Ol)[off >> 1] = lo;
                }
            }
        }
}

// ---------------- aux kernels ----------------
__device__ __forceinline__ void hsplit(float v, __half* h, __half* l, size_t i) {
    const __half hv = __float2half_rn(v);
    h[i] = hv;
    l[i] = __float2half_rn(v - __half2float(hv));
}
__global__ void prep_k(const float* __restrict__ eps, const float* __restrict__ W2,
                       const float* __restrict__ W3, const float* __restrict__ W1,
                       __half* eph, __half* epl,
                       __half* w2f, __half* w3f,
                       __half* w2tf, __half* w1ytf, __half* w3tf) {
    int i = blockIdx.x * 256 + threadIdx.x;
    if (i < Bb * Dd) { hsplit(eps[i], eph, epl, i); return; }
    i -= Bb * Dd;
    if (i < Hh * Hh) { w2f[i] = __float2half_rn(W2[i]); return; }
    i -= Hh * Hh;
    if (i < Hh * Dd) { w3f[i] = __float2half_rn(W3[i]); return; }
    i -= Hh * Dd;
    if (i < Hh * Hh) {
        const int r = i / Hh, c = i % Hh;
        w2tf[(size_t)c * Hh + r] = __float2half_rn(W2[i]);
        return;
    }
    i -= Hh * Hh;
    if (i < Dd * Hh) {
        const int r = i / Hh, c = i % Hh;
        w1ytf[(size_t)c * Dd + r] = __float2half_rn(W1[i]);
        return;
    }
    i -= Dd * Hh;
    if (i < Hh * Dd) {
        const int r = i / Dd, c = i % Dd;
        w3tf[(size_t)c * Hh + r] = __float2half_rn(W3[i]);
    }
}
__global__ void cbias_k(const float* __restrict__ cond, const float* __restrict__ W1c,
                        const float* __restrict__ b1, float* __restrict__ cb) {
    const int m = blockIdx.x;
    const int n = threadIdx.x * 4;
    float4 acc = *(const float4*)(b1 + n);
    #pragma unroll
    for (int k = 0; k < Cc; k++) {
        const float c = cond[m * Cc + k];
        const float4 w = *(const float4*)(W1c + (size_t)k * Hh + n);
        acc.x = fmaf(c, w.x, acc.x); acc.y = fmaf(c, w.y, acc.y);
        acc.z = fmaf(c, w.z, acc.z); acc.w = fmaf(c, w.w, acc.w);
    }
    *(float4*)(cb + (size_t)m * Hh + n) = acc;
}
__global__ void init_k(const float* __restrict__ x, float* __restrict__ y,
                       __half* __restrict__ yinh, __half* __restrict__ yinl,
                       float* __restrict__ ld) {
    const int i = blockIdx.x * blockDim.x + threadIdx.x;
    if (i < Bb * Dd) {
        const float v = x[i];
        y[i] = v;
        hsplit(v, yinh, yinl, i);
    }
    if (i < Bb) ld[i] = 0.f;
}
__global__ void out_k(const float* __restrict__ y, const float* __restrict__ ld,
                      const float* __restrict__ psum, float coef, float* __restrict__ out) {
    const int i = blockIdx.x * blockDim.x + threadIdx.x;
    if (i >= Bb * (Dd + 1)) return;
    const int m = i / (Dd + 1), c = i % (Dd + 1);
    if (c < Dd) {
        out[i] = y[(size_t)m * Dd + c];
    } else {
        float s = 0.f;
        #pragma unroll
        for (int c2 = 0; c2 < 8; c2++) s += psum[c2 * Bb + m];
        out[i] = ld[m] + coef * s;
    }
}

// ---------------- host ----------------
extern "C" void kernel_launch(void* const* d_in, const int* in_sizes, int n_in,
                              void* d_out, int out_size) {
    const float* x    = (const float*)d_in[0];
    const float* cond = (const float*)d_in[1];
    const float* eps  = (const float*)d_in[2];
    const float* W1   = (const float*)d_in[3];
    const float* b1   = (const float*)d_in[4];
    const float* W2   = (const float*)d_in[5];
    const float* b2   = (const float*)d_in[6];
    const float* W3   = (const float*)d_in[7];
    const float* b3   = (const float*)d_in[8];
    float* out = (float*)d_out;

    cudaFuncSetAttribute(mma_k<0>, cudaFuncAttributeMaxDynamicSharedMemorySize, SMEM_SM);
    cudaFuncSetAttribute(mma_k<1>, cudaFuncAttributeMaxDynamicSharedMemorySize, SMEM_SM);
    cudaFuncSetAttribute(mma_k<2>, cudaFuncAttributeMaxDynamicSharedMemorySize, SMEM_SM);
    cudaFuncSetAttribute(mma_k<3>, cudaFuncAttributeMaxDynamicSharedMemorySize, SMEM_SM);

    #define SYM(T, v, s) T* v; { void* _p; cudaGetSymbolAddress(&_p, s); v = (T*)_p; }
    SYM(float, y, g_y) SYM(float, yacc, g_yacc) SYM(float, cb, g_cb)
    SYM(float, G3, g_G3) SYM(float, E1, g_E1) SYM(float, ld, g_ld) SYM(float, psum, g_psum)
    SYM(__half, h1h, g_h1h) SYM(__half, h1l, g_h1l)
    SYM(__half, h2h, g_h2h) SYM(__half, h2l, g_h2l)
    SYM(__half, yinh, g_yinh) SYM(__half, yinl, g_yinl)
    SYM(__half, epsh, g_epsh) SYM(__half, epsl, g_epsl)
    SYM(__half, W2f, g_W2f) SYM(__half, W2Tf, g_W2Tf)
    SYM(__half, W3f, g_W3f) SYM(__half, W3Tf, g_W3Tf)
    SYM(__half, W1yTf, g_W1yTf)
    #undef SYM

    init_k<<<(Bb * Dd + 255) / 256, 256>>>(x, y, yinh, yinl, ld);

    constexpr int PREP_N = Bb * Dd + 2 * Hh * Hh + 3 * Hh * Dd;
    const float dt = 1.0f / NS;
    float prev_cl = 0.f;

    for (int ib = 0; ib < NB; ib++) {
        const float* W1b  = W1 + (size_t)ib * (Dd + Cc + 1) * Hh;
        const float* b1b  = b1 + (size_t)ib * Hh;
        const float* W2b  = W2 + (size_t)ib * Hh * Hh;
        const float* b2b  = b2 + (size_t)ib * Hh;
        const float* W3b  = W3 + (size_t)ib * Hh * Dd;
        const float* b3b  = b3 + (size_t)ib * Dd;
        const float* epsb = eps + (size_t)ib * Bb * Dd;
        float* cbb = cb + (size_t)ib * Bb * Hh;
        float* G3b = G3 + (size_t)ib * Bb * Hh;
        float* E1b = E1 + (size_t)ib * Bb * Hh;
        __half *eph = epsh + (size_t)ib * Bb * Dd, *epl = epsl + (size_t)ib * Bb * Dd;
        __half* w2f  = W2f  + (size_t)ib * Hh * Hh;
        __half* w2tf = W2Tf + (size_t)ib * Hh * Hh;
        __half* w3f  = W3f  + (size_t)ib * Hh * Dd;
        __half* w3tf = W3Tf + (size_t)ib * Dd * Hh;
        __half* w1ytf = W1yTf + (size_t)ib * Hh * Dd;

        prep_k<<<(PREP_N + 255) / 256, 256>>>(epsb, W2b, W3b, W1b,
            eph, epl, w2f, w3f, w2tf, w1ytf, w3tf);
        cbias_k<<<Bb, 128>>>(cond, W1b + (size_t)Dd * Hh, b1b, cbb);

        {   // merged G3 (by<8) + E1 (by>=8)
            P p{}; p.Ah = eph; p.Al = epl;
            p.Bf = w3f; p.C = G3b;
            p.B2f = w1ytf; p.C2 = E1b;
            mma_k<0><<<dim3(32, 16), 256, SMEM_SM>>>(p);
        }

        for (int is = 0; is < NS; is++) {
            const float tbase = is * dt;
            for (int st = 1; st <= 4; st++) {
                const float t = tbase + (st == 1 ? 0.f : (st == 4 ? dt : 0.5f * dt));
                const float cacc = (st == 1 || st == 4) ? dt / 6.f : dt / 3.f;
                const float cin  = (st == 3) ? dt : 0.5f * dt;

                {   // F1 + fold rider
                    P p{}; p.Ah = yinh; p.Al = yinl; p.Bf = w1ytf;
                    p.cbias = cbb; p.w1t = W1b + (size_t)(Dd + Cc) * Hh; p.t = t;
                    p.Oh = h1h; p.Ol = h1l;
                    p.foldcoef = prev_cl; p.ld = ld; p.psum = psum;
                    mma_k<1><<<dim3(32, 9), 256, SMEM_SM>>>(p);
                }
                {   // F2
                    P p{}; p.Ah = h1h; p.Al = h1l; p.Bf = w2tf;
                    p.bias = b2b; p.Oh = h2h; p.Ol = h2l;
                    mma_k<2><<<dim3(32, 8), 256, SMEM_SM>>>(p);
                }
                {   // FUSED: B2 fp16 + logdet dot (by<8), F3 + RK4 (by==8)
                    P p{};
                    p.Amask = G3b; p.Mh = h2h; p.Ml = h2l; p.W2f = w2f;
                    p.F3Ah = h2h; p.F3Al = h2l; p.F3Bf = w3tf;
                    p.h1h = h1h; p.h1l = h1l; p.E1 = E1b; p.psum = psum;
                    p.b3 = b3b; p.y = y; p.yacc = yacc; p.Oh = yinh; p.Ol = yinl;
                    p.stage = st; p.cacc = cacc; p.cin = cin;
                    mma_k<3><<<dim3(32, 9), 256, SMEM_SM>>>(p);
                }
                prev_cl = cacc;
            }
        }
    }

    out_k<<<(Bb * (Dd + 1) + 255) / 256, 256>>>(y, ld, psum, prev_cl, out);
}

// round 12
// speedup vs baseline: 1.8459x; 1.3685x over previous
#include <cuda_runtime.h>
#include <cuda_fp16.h>
#include <math.h>
#include <stdint.h>

namespace {
constexpr int Bb = 4096, Dd = 64, Cc = 16, Hh = 512, NB = 2, NS = 8;
constexpr int SAS = 40;               // smem row stride in halves (80B)
constexpr int AT = 128 * SAS;         // A halves per buffer (per plane)
constexpr int BT = 64 * SAS;          // B halves per buffer
constexpr int SMEM_SM = (2 * AT + 2 * AT + 2 * BT) * 2 + 1024;
}

// ---------------- device scratch ----------------
__device__ __align__(16) __half g_h1h[Bb * Hh];                 // single plane
__device__ __align__(16) __half g_h2h[Bb * Hh];                 // single plane
__device__ __align__(16) __half g_mAh[Bb * Hh];                 // B2 masked A plane
__device__ __align__(16) __half g_yinh[Bb * Dd], g_yinl[Bb * Dd];
__device__ __align__(16) float g_y[Bb * Dd], g_yacc[Bb * Dd];
__device__ __align__(16) float g_cb[NB * Bb * Hh], g_G3[NB * Bb * Hh], g_E1[NB * Bb * Hh];
__device__ __align__(16) float g_ld[Bb], g_psum[8 * Bb];
__device__ __align__(16) __half g_epsh[NB * Bb * Dd], g_epsl[NB * Bb * Dd];
__device__ __align__(16) __half g_W2f  [NB * Hh * Hh];   // [n][k] B2
__device__ __align__(16) __half g_W2Tf [NB * Hh * Hh];   // [n][k] F2
__device__ __align__(16) __half g_W3f  [NB * Hh * Dd];   // [512][64] G3
__device__ __align__(16) __half g_W3Tf [NB * Dd * Hh];   // [64][512] F3
__device__ __align__(16) __half g_W1yTf[NB * Hh * Dd];   // [512][64] F1/E1

// ---------------- helpers ----------------
__device__ __forceinline__ uint32_t sptr(const void* p) {
    return (uint32_t)__cvta_generic_to_shared(p);
}
__device__ __forceinline__ void ldm4(uint32_t a, uint32_t& r0, uint32_t& r1,
                                     uint32_t& r2, uint32_t& r3) {
    asm volatile("ldmatrix.sync.aligned.m8n8.x4.shared.b16 {%0,%1,%2,%3}, [%4];"
                 : "=r"(r0), "=r"(r1), "=r"(r2), "=r"(r3) : "r"(a));
}
__device__ __forceinline__ void mma_f16(float* c, const uint32_t* a, uint32_t b0, uint32_t b1) {
    asm volatile("mma.sync.aligned.m16n8k16.row.col.f32.f16.f16.f32 "
                 "{%0,%1,%2,%3}, {%4,%5,%6,%7}, {%8,%9}, {%0,%1,%2,%3};"
                 : "+f"(c[0]), "+f"(c[1]), "+f"(c[2]), "+f"(c[3])
                 : "r"(a[0]), "r"(a[1]), "r"(a[2]), "r"(a[3]), "r"(b0), "r"(b1));
}
__device__ __forceinline__ void cp16(void* dst, const void* src) {
    asm volatile("cp.async.cg.shared.global [%0], [%1], 16;"
                 :: "r"(sptr(dst)), "l"(src));
}
#define CP_COMMIT() asm volatile("cp.async.commit_group;" ::: "memory")
#define CP_WAIT1()  asm volatile("cp.async.wait_group 1;" ::: "memory")
#define CP_WAIT0()  asm volatile("cp.async.wait_group 0;" ::: "memory")

__device__ __forceinline__ unsigned pack_h2(float v0, float v1, unsigned& lo_out) {
    __half h0 = __float2half_rn(v0), h1 = __float2half_rn(v1);
    __half l0 = __float2half_rn(v0 - __half2float(h0));
    __half l1 = __float2half_rn(v1 - __half2float(h1));
    lo_out = (unsigned)__half_as_ushort(l0) | ((unsigned)__half_as_ushort(l1) << 16);
    return (unsigned)__half_as_ushort(h0) | ((unsigned)__half_as_ushort(h1) << 16);
}
__device__ __forceinline__ unsigned pack_h1(float v0, float v1) {
    return (unsigned)__half_as_ushort(__float2half_rn(v0))
         | ((unsigned)__half_as_ushort(__float2half_rn(v1)) << 16);
}
__device__ __forceinline__ float up16(unsigned w, int half) {
    return __half2float(__ushort_as_half((unsigned short)(half ? (w >> 16) : w)));
}
__device__ __forceinline__ float ftanh(float x) {
    const float cx = fminf(fmaxf(x, -15.f), 15.f);
    const float e = __expf(2.f * cx);
    return __fdividef(e - 1.f, e + 1.f);
}

struct P {
    const __half *Ah, *Al;          // A planes (Al unused in single-plane modes)
    const __half *Bf, *B2f;         // weight planes
    const float *G3;                // fp32 G3 (F2 epilogue mask)
    __half *mA;                     // masked-A plane out (F2)
    const __half *F3Ah, *F3Bf;
    float *C, *C2;
    const float *cbias, *w1t, *bias, *b3, *E1;
    const __half *h1h;
    __half *Oh, *Ol;
    float *y, *yacc, *ld, *psum;
    int stage;
    float t, cacc, cin, foldcoef;
};

// 128x64 CTA tile, 256 threads (8 warps: wm=wid&3, wn=wid>>2).
// MODE 0: by<8 G3 / by>=8 E1 (K=64, A=eps 2-plane, fp32 C)           grid (32,16)
// MODE 1: by<8 F1 (K=64, A=yin 2-plane, tanh -> h1h); by==8 fold      grid (32,9)
// MODE 2: F2 (K=512, A=h1h 1-plane, tanh -> h2h + mA)                 grid (32,8)
// MODE 3: by<8 B2 (K=512, A=mA 1-plane, logdet dot) / by==8 F3 + RK4  grid (32,9)
template <int MODE>
__global__ void __launch_bounds__(256, 3) mma_k(P p) {
    extern __shared__ __align__(16) char dynsmem[];
    __half* sAh = (__half*)dynsmem;
    __half* sAl = sAh + 2 * AT;
    __half* sBh = sAl + 2 * AT;
    float* red = (float*)(sBh + 2 * BT);

    const int tid = threadIdx.x, lane = tid & 31, wid = tid >> 5;
    const int wm = wid & 3, wn = wid >> 2;
    const int m0 = blockIdx.x * 128, by = blockIdx.y;

    if (MODE == 1 && by == 8) {   // fold rider
        if (p.foldcoef != 0.f && tid < 128) {
            const int m = m0 + tid;
            float s = 0.f;
            #pragma unroll
            for (int c = 0; c < 8; c++) s += p.psum[c * Bb + m];
            p.ld[m] += p.foldcoef * s;
        }
        return;
    }

    const bool isF3 = (MODE == 3 && by == 8);
    constexpr bool twoA = (MODE <= 1);   // eps / yin use hi+lo planes

    const __half *Ah, *Al = nullptr, *Bfp;
    int lda, ldb, K, n0;
    float* C0 = nullptr;
    if (MODE == 0) {
        K = 64; lda = 64; ldb = 64;
        Ah = p.Ah; Al = p.Al;
        if (by < 8) { Bfp = p.Bf; C0 = p.C; n0 = by * 64; }
        else        { Bfp = p.B2f; C0 = p.C2; n0 = (by - 8) * 64; }
    } else if (MODE == 1) {
        K = 64; lda = 64; ldb = 64; n0 = by * 64;
        Ah = p.Ah; Al = p.Al; Bfp = p.Bf;
    } else if (MODE == 2) {
        K = 512; lda = 512; ldb = 512; n0 = by * 64;
        Ah = p.Ah; Bfp = p.Bf;
    } else if (!isF3) {
        K = 512; lda = 512; ldb = 512; n0 = by * 64;
        Ah = p.Ah; Bfp = p.Bf;
    } else {
        K = 512; lda = 512; ldb = 512; n0 = 0;
        Ah = p.F3Ah; Bfp = p.F3Bf;
    }
    const int NT = K / 32;

    auto issue = [&](int kt) {
        const int buf = kt & 1;
        const int k0 = kt * 32;
        if (twoA) {
            #pragma unroll
            for (int c = tid; c < 1024; c += 256) {
                const int plane = c >> 9, cc = c & 511;
                const int row = cc >> 2, ku = cc & 3;
                cp16((plane ? sAl : sAh) + buf * AT + row * SAS + ku * 8,
                     (plane ? Al : Ah) + (size_t)(m0 + row) * lda + k0 + ku * 8);
            }
        } else {
            #pragma unroll
            for (int c = tid; c < 512; c += 256) {
                const int row = c >> 2, ku = c & 3;
                cp16(sAh + buf * AT + row * SAS + ku * 8,
                     Ah + (size_t)(m0 + row) * lda + k0 + ku * 8);
            }
        }
        {   // B single plane: 64 rows x 4 chunks = 256, one per thread
            const int row = tid >> 2, ku = tid & 3;
            cp16(sBh + buf * BT + row * SAS + ku * 8,
                 Bfp + (size_t)(n0 + row) * ldb + k0 + ku * 8);
        }
        CP_COMMIT();
    };

    const int l7 = lane & 7;
    const int aro = l7 + ((lane >> 3) & 1) * 8;
    const int aco = (lane >> 4) * 8;
    const int bro = l7 + (lane >> 4) * 8;
    const int bco = ((lane >> 3) & 1) * 8;

    float acc[2][4][4] = {};

    auto compute = [&](int buf) {
        const uint32_t bAh = sptr(sAh + buf * AT);
        const uint32_t bAl = sptr(sAl + buf * AT);
        const uint32_t bBh = sptr(sBh + buf * BT);
        #pragma unroll
        for (int kk = 0; kk < 2; kk++) {
            uint32_t ah[2][4], al[2][4], bh[2][4];
            #pragma unroll
            for (int mt = 0; mt < 2; mt++) {
                const uint32_t off = ((wm * 32 + mt * 16 + aro) * SAS + kk * 16 + aco) * 2;
                ldm4(bAh + off, ah[mt][0], ah[mt][1], ah[mt][2], ah[mt][3]);
                if (twoA) ldm4(bAl + off, al[mt][0], al[mt][1], al[mt][2], al[mt][3]);
            }
            #pragma unroll
            for (int pn = 0; pn < 2; pn++) {
                const uint32_t off = ((wn * 32 + pn * 16 + bro) * SAS + kk * 16 + bco) * 2;
                ldm4(bBh + off, bh[pn][0], bh[pn][1], bh[pn][2], bh[pn][3]);
            }
            #pragma unroll
            for (int mt = 0; mt < 2; mt++)
                #pragma unroll
                for (int nt = 0; nt < 4; nt++) {
                    const uint32_t b0 = bh[nt >> 1][(nt & 1) * 2], b1 = bh[nt >> 1][(nt & 1) * 2 + 1];
                    mma_f16(acc[mt][nt], ah[mt], b0, b1);
                    if (twoA) mma_f16(acc[mt][nt], al[mt], b0, b1);
                }
        }
    };

    issue(0);
    for (int kt = 0; kt < NT; kt++) {
        if (kt + 1 < NT) { issue(kt + 1); CP_WAIT1(); } else { CP_WAIT0(); }
        __syncthreads();
        compute(kt & 1);
        __syncthreads();
    }

    // ---- epilogues ----
    const int g = lane >> 2, tt = lane & 3;

    if (MODE == 3 && !isF3) {   // B2 logdet dot
        float s[4] = {0.f, 0.f, 0.f, 0.f};
        #pragma unroll
        for (int mt = 0; mt < 2; mt++)
            #pragma unroll
            for (int nt = 0; nt < 4; nt++) {
                const int c = n0 + wn * 32 + nt * 8 + tt * 2;
                #pragma unroll
                for (int hr = 0; hr < 2; hr++) {
                    const int r = m0 + wm * 32 + mt * 16 + g + hr * 8;
                    const size_t off = (size_t)r * 512 + c;
                    const unsigned hh = *(const unsigned*)&p.h1h[off];
                    const float2 e = *(const float2*)&p.E1[off];
                    const float h0 = up16(hh, 0), h1v = up16(hh, 1);
                    s[mt * 2 + hr] += acc[mt][nt][hr * 2 + 0] * (1.f - h0 * h0) * e.x
                                    + acc[mt][nt][hr * 2 + 1] * (1.f - h1v * h1v) * e.y;
                }
            }
        #pragma unroll
        for (int i = 0; i < 4; i++) {
            s[i] += __shfl_xor_sync(0xffffffffu, s[i], 1);
            s[i] += __shfl_xor_sync(0xffffffffu, s[i], 2);
        }
        if (tt == 0) {
            #pragma unroll
            for (int mt = 0; mt < 2; mt++)
                #pragma unroll
                for (int hr = 0; hr < 2; hr++)
                    red[(wm * 32 + mt * 16 + g + hr * 8) * 2 + wn] = s[mt * 2 + hr];
        }
        __syncthreads();
        if (tid < 128)
            p.psum[(size_t)by * Bb + m0 + tid] = red[tid * 2] + red[tid * 2 + 1];
        return;
    }

    if (isF3) {   // F3 + RK4 (yin kept as 2 planes)
        unsigned* yinhU = (unsigned*)p.Oh;
        unsigned* yinlU = (unsigned*)p.Ol;
        #pragma unroll
        for (int mt = 0; mt < 2; mt++)
            #pragma unroll
            for (int nt = 0; nt < 4; nt++) {
                const int c = wn * 32 + nt * 8 + tt * 2;
                const float2 b3v = *(const float2*)&p.b3[c];
                #pragma unroll
                for (int hr = 0; hr < 2; hr++) {
                    const int r = m0 + wm * 32 + mt * 16 + g + hr * 8;
                    const size_t idx = (size_t)r * 64 + c;
                    const float kv0 = acc[mt][nt][hr * 2 + 0] + b3v.x;
                    const float kv1 = acc[mt][nt][hr * 2 + 1] + b3v.y;
                    const float2 base = (p.stage == 1) ? *(const float2*)&p.y[idx]
                                                       : *(const float2*)&p.yacc[idx];
                    const float ya0 = base.x + p.cacc * kv0;
                    const float ya1 = base.y + p.cacc * kv1;
                    float yi0, yi1;
                    if (p.stage == 4) {
                        *(float2*)&p.y[idx] = make_float2(ya0, ya1);
                        yi0 = ya0; yi1 = ya1;
                    } else {
                        *(float2*)&p.yacc[idx] = make_float2(ya0, ya1);
                        const float2 yv = *(const float2*)&p.y[idx];
                        yi0 = yv.x + p.cin * kv0;
                        yi1 = yv.y + p.cin * kv1;
                    }
                    unsigned lo, hi = pack_h2(yi0, yi1, lo);
                    yinhU[idx >> 1] = hi;
                    yinlU[idx >> 1] = lo;
                }
            }
        return;
    }

    // MODE 0/1/2 fragment epilogues
    #pragma unroll
    for (int mt = 0; mt < 2; mt++)
        #pragma unroll
        for (int nt = 0; nt < 4; nt++) {
            const int c = n0 + wn * 32 + nt * 8 + tt * 2;
            #pragma unroll
            for (int hr = 0; hr < 2; hr++) {
                const int r = m0 + wm * 32 + mt * 16 + g + hr * 8;
                float v0 = acc[mt][nt][hr * 2 + 0];
                float v1 = acc[mt][nt][hr * 2 + 1];
                const size_t off = (size_t)r * 512 + c;
                if (MODE == 0) {
                    *(float2*)&C0[off] = make_float2(v0, v1);
                } else if (MODE == 1) {
                    const float2 cb = *(const float2*)&p.cbias[off];
                    const float2 wt = *(const float2*)&p.w1t[c];
                    v0 = ftanh(v0 + cb.x + p.t * wt.x);
                    v1 = ftanh(v1 + cb.y + p.t * wt.y);
                    ((unsigned*)p.Oh)[off >> 1] = pack_h1(v0, v1);
                } else {   // MODE 2: tanh -> h2h, and mA = G3*(1-h2^2)
                    const float2 bi = *(const float2*)&p.bias[c];
                    v0 = ftanh(v0 + bi.x);
                    v1 = ftanh(v1 + bi.y);
                    ((unsigned*)p.Oh)[off >> 1] = pack_h1(v0, v1);
                    const float2 gv = *(const float2*)&p.G3[off];
                    ((unsigned*)p.mA)[off >> 1] =
                        pack_h1(gv.x * (1.f - v0 * v0), gv.y * (1.f - v1 * v1));
                }
            }
        }
}

// ---------------- aux kernels ----------------
__device__ __forceinline__ void hsplit(float v, __half* h, __half* l, size_t i) {
    const __half hv = __float2half_rn(v);
    h[i] = hv;
    l[i] = __float2half_rn(v - __half2float(hv));
}
__global__ void prep_k(const float* __restrict__ eps, const float* __restrict__ W2,
                       const float* __restrict__ W3, const float* __restrict__ W1,
                       __half* eph, __half* epl,
                       __half* w2f, __half* w3f,
                       __half* w2tf, __half* w1ytf, __half* w3tf) {
    int i = blockIdx.x * 256 + threadIdx.x;
    if (i < Bb * Dd) { hsplit(eps[i], eph, epl, i); return; }
    i -= Bb * Dd;
    if (i < Hh * Hh) { w2f[i] = __float2half_rn(W2[i]); return; }
    i -= Hh * Hh;
    if (i < Hh * Dd) { w3f[i] = __float2half_rn(W3[i]); return; }
    i -= Hh * Dd;
    if (i < Hh * Hh) {
        const int r = i / Hh, c = i % Hh;
        w2tf[(size_t)c * Hh + r] = __float2half_rn(W2[i]);
        return;
    }
    i -= Hh * Hh;
    if (i < Dd * Hh) {
        const int r = i / Hh, c = i % Hh;
        w1ytf[(size_t)c * Dd + r] = __float2half_rn(W1[i]);
        return;
    }
    i -= Dd * Hh;
    if (i < Hh * Dd) {
        const int r = i / Dd, c = i % Dd;
        w3tf[(size_t)c * Hh + r] = __float2half_rn(W3[i]);
    }
}
__global__ void cbias_k(const float* __restrict__ cond, const float* __restrict__ W1c,
                        const float* __restrict__ b1, float* __restrict__ cb) {
    const int m = blockIdx.x;
    const int n = threadIdx.x * 4;
    float4 acc = *(const float4*)(b1 + n);
    #pragma unroll
    for (int k = 0; k < Cc; k++) {
        const float c = cond[m * Cc + k];
        const float4 w = *(const float4*)(W1c + (size_t)k * Hh + n);
        acc.x = fmaf(c, w.x, acc.x); acc.y = fmaf(c, w.y, acc.y);
        acc.z = fmaf(c, w.z, acc.z); acc.w = fmaf(c, w.w, acc.w);
    }
    *(float4*)(cb + (size_t)m * Hh + n) = acc;
}
__global__ void init_k(const float* __restrict__ x, float* __restrict__ y,
                       __half* __restrict__ yinh, __half* __restrict__ yinl,
                       float* __restrict__ ld) {
    const int i = blockIdx.x * blockDim.x + threadIdx.x;
    if (i < Bb * Dd) {
        const float v = x[i];
        y[i] = v;
        hsplit(v, yinh, yinl, i);
    }
    if (i < Bb) ld[i] = 0.f;
}
__global__ void out_k(const float* __restrict__ y, const float* __restrict__ ld,
                      const float* __restrict__ psum, float coef, float* __restrict__ out) {
    const int i = blockIdx.x * blockDim.x + threadIdx.x;
    if (i >= Bb * (Dd + 1)) return;
    const int m = i / (Dd + 1), c = i % (Dd + 1);
    if (c < Dd) {
        out[i] = y[(size_t)m * Dd + c];
    } else {
        float s = 0.f;
        #pragma unroll
        for (int c2 = 0; c2 < 8; c2++) s += psum[c2 * Bb + m];
        out[i] = ld[m] + coef * s;
    }
}

// ---------------- host ----------------
extern "C" void kernel_launch(void* const* d_in, const int* in_sizes, int n_in,
                              void* d_out, int out_size) {
    const float* x    = (const float*)d_in[0];
    const float* cond = (const float*)d_in[1];
    const float* eps  = (const float*)d_in[2];
    const float* W1   = (const float*)d_in[3];
    const float* b1   = (const float*)d_in[4];
    const float* W2   = (const float*)d_in[5];
    const float* b2   = (const float*)d_in[6];
    const float* W3   = (const float*)d_in[7];
    const float* b3   = (const float*)d_in[8];
    float* out = (float*)d_out;

    cudaFuncSetAttribute(mma_k<0>, cudaFuncAttributeMaxDynamicSharedMemorySize, SMEM_SM);
    cudaFuncSetAttribute(mma_k<1>, cudaFuncAttributeMaxDynamicSharedMemorySize, SMEM_SM);
    cudaFuncSetAttribute(mma_k<2>, cudaFuncAttributeMaxDynamicSharedMemorySize, SMEM_SM);
    cudaFuncSetAttribute(mma_k<3>, cudaFuncAttributeMaxDynamicSharedMemorySize, SMEM_SM);

    #define SYM(T, v, s) T* v; { void* _p; cudaGetSymbolAddress(&_p, s); v = (T*)_p; }
    SYM(float, y, g_y) SYM(float, yacc, g_yacc) SYM(float, cb, g_cb)
    SYM(float, G3, g_G3) SYM(float, E1, g_E1) SYM(float, ld, g_ld) SYM(float, psum, g_psum)
    SYM(__half, h1h, g_h1h) SYM(__half, h2h, g_h2h) SYM(__half, mAh, g_mAh)
    SYM(__half, yinh, g_yinh) SYM(__half, yinl, g_yinl)
    SYM(__half, epsh, g_epsh) SYM(__half, epsl, g_epsl)
    SYM(__half, W2f, g_W2f) SYM(__half, W2Tf, g_W2Tf)
    SYM(__half, W3f, g_W3f) SYM(__half, W3Tf, g_W3Tf)
    SYM(__half, W1yTf, g_W1yTf)
    #undef SYM

    init_k<<<(Bb * Dd + 255) / 256, 256>>>(x, y, yinh, yinl, ld);

    constexpr int PREP_N = Bb * Dd + 2 * Hh * Hh + 3 * Hh * Dd;
    const float dt = 1.0f / NS;
    float prev_cl = 0.f;

    for (int ib = 0; ib < NB; ib++) {
        const float* W1b  = W1 + (size_t)ib * (Dd + Cc + 1) * Hh;
        const float* b1b  = b1 + (size_t)ib * Hh;
        const float* W2b  = W2 + (size_t)ib * Hh * Hh;
        const float* b2b  = b2 + (size_t)ib * Hh;
        const float* W3b  = W3 + (size_t)ib * Hh * Dd;
        const float* b3b  = b3 + (size_t)ib * Dd;
        const float* epsb = eps + (size_t)ib * Bb * Dd;
        float* cbb = cb + (size_t)ib * Bb * Hh;
        float* G3b = G3 + (size_t)ib * Bb * Hh;
        float* E1b = E1 + (size_t)ib * Bb * Hh;
        __half *eph = epsh + (size_t)ib * Bb * Dd, *epl = epsl + (size_t)ib * Bb * Dd;
        __half* w2f  = W2f  + (size_t)ib * Hh * Hh;
        __half* w2tf = W2Tf + (size_t)ib * Hh * Hh;
        __half* w3f  = W3f  + (size_t)ib * Hh * Dd;
        __half* w3tf = W3Tf + (size_t)ib * Dd * Hh;
        __half* w1ytf = W1yTf + (size_t)ib * Hh * Dd;

        prep_k<<<(PREP_N + 255) / 256, 256>>>(epsb, W2b, W3b, W1b,
            eph, epl, w2f, w3f, w2tf, w1ytf, w3tf);
        cbias_k<<<Bb, 128>>>(cond, W1b + (size_t)Dd * Hh, b1b, cbb);

        {   // merged G3 (by<8) + E1 (by>=8)
            P p{}; p.Ah = eph; p.Al = epl;
            p.Bf = w3f; p.C = G3b;
            p.B2f = w1ytf; p.C2 = E1b;
            mma_k<0><<<dim3(32, 16), 256, SMEM_SM>>>(p);
        }

        for (int is = 0; is < NS; is++) {
            const float tbase = is * dt;
            for (int st = 1; st <= 4; st++) {
                const float t = tbase + (st == 1 ? 0.f : (st == 4 ? dt : 0.5f * dt));
                const float cacc = (st == 1 || st == 4) ? dt / 6.f : dt / 3.f;
                const float cin  = (st == 3) ? dt : 0.5f * dt;

                {   // F1 + fold rider
                    P p{}; p.Ah = yinh; p.Al = yinl; p.Bf = w1ytf;
                    p.cbias = cbb; p.w1t = W1b + (size_t)(Dd + Cc) * Hh; p.t = t;
                    p.Oh = h1h;
                    p.foldcoef = prev_cl; p.ld = ld; p.psum = psum;
                    mma_k<1><<<dim3(32, 9), 256, SMEM_SM>>>(p);
                }
                {   // F2: tanh -> h2h plane + mA masked plane
                    P p{}; p.Ah = h1h; p.Bf = w2tf;
                    p.bias = b2b; p.Oh = h2h; p.G3 = G3b; p.mA = mAh;
                    mma_k<2><<<dim3(32, 8), 256, SMEM_SM>>>(p);
                }
                {   // FUSED: B2 (A=mA) + logdet dot (by<8), F3 + RK4 (by==8)
                    P p{};
                    p.Ah = mAh; p.Bf = w2f;
                    p.F3Ah = h2h; p.F3Bf = w3tf;
                    p.h1h = h1h; p.E1 = E1b; p.psum = psum;
                    p.b3 = b3b; p.y = y; p.yacc = yacc; p.Oh = yinh; p.Ol = yinl;
                    p.stage = st; p.cacc = cacc; p.cin = cin;
                    mma_k<3><<<dim3(32, 9), 256, SMEM_SM>>>(p);
                }
                prev_cl = cacc;
            }
        }
    }

    out_k<<<(Bb * (Dd + 1) + 255) / 256, 256>>>(y, ld, psum, prev_cl, out);
}

// round 13
// speedup vs baseline: 1.9936x; 1.0800x over previous
#include <cuda_runtime.h>
#include <cuda_fp16.h>
#include <math.h>
#include <stdint.h>

namespace {
constexpr int Bb = 4096, Dd = 64, Cc = 16, Hh = 512, NB = 2, NS = 8;
constexpr int SAS = 40;               // smem row stride in halves (80B)
constexpr int AT = 128 * SAS;         // A halves per buffer (per plane)
constexpr int BT = 64 * SAS;          // B halves per buffer
constexpr int SMEM_SM  = (2 * AT + 2 * AT + 2 * BT) * 2 + 1024;   // small kernel (2-plane A, 2 bufs)
constexpr int SMEM_BIG = (3 * (AT + BT)) * 2 + 1024;              // big kernel (1-plane A, 3 bufs)
}

// ---------------- device scratch ----------------
__device__ __align__(16) __half g_h1h[Bb * Hh];                 // single plane
__device__ __align__(16) __half g_h2h[Bb * Hh];                 // single plane
__device__ __align__(16) __half g_mAh[Bb * Hh];                 // B2 masked A plane
__device__ __align__(16) __half g_yinh[Bb * Dd], g_yinl[Bb * Dd];
__device__ __align__(16) float g_y[Bb * Dd], g_yacc[Bb * Dd];
__device__ __align__(16) float g_cb[NB * Bb * Hh], g_G3[NB * Bb * Hh], g_E1[NB * Bb * Hh];
__device__ __align__(16) float g_ld[Bb], g_psum[8 * Bb];
__device__ __align__(16) __half g_epsh[NB * Bb * Dd], g_epsl[NB * Bb * Dd];
__device__ __align__(16) __half g_W2f  [NB * Hh * Hh];   // [n][k] B2
__device__ __align__(16) __half g_W2Tf [NB * Hh * Hh];   // [n][k] F2
__device__ __align__(16) __half g_W3f  [NB * Hh * Dd];   // [512][64] G3
__device__ __align__(16) __half g_W3Tf [NB * Dd * Hh];   // [64][512] F3
__device__ __align__(16) __half g_W1yTf[NB * Hh * Dd];   // [512][64] F1/E1

// ---------------- helpers ----------------
__device__ __forceinline__ uint32_t sptr(const void* p) {
    return (uint32_t)__cvta_generic_to_shared(p);
}
__device__ __forceinline__ void ldm4(uint32_t a, uint32_t& r0, uint32_t& r1,
                                     uint32_t& r2, uint32_t& r3) {
    asm volatile("ldmatrix.sync.aligned.m8n8.x4.shared.b16 {%0,%1,%2,%3}, [%4];"
                 : "=r"(r0), "=r"(r1), "=r"(r2), "=r"(r3) : "r"(a));
}
__device__ __forceinline__ void mma_f16(float* c, const uint32_t* a, uint32_t b0, uint32_t b1) {
    asm volatile("mma.sync.aligned.m16n8k16.row.col.f32.f16.f16.f32 "
                 "{%0,%1,%2,%3}, {%4,%5,%6,%7}, {%8,%9}, {%0,%1,%2,%3};"
                 : "+f"(c[0]), "+f"(c[1]), "+f"(c[2]), "+f"(c[3])
                 : "r"(a[0]), "r"(a[1]), "r"(a[2]), "r"(a[3]), "r"(b0), "r"(b1));
}
__device__ __forceinline__ void cp16(void* dst, const void* src) {
    asm volatile("cp.async.cg.shared.global [%0], [%1], 16;"
                 :: "r"(sptr(dst)), "l"(src));
}
#define CP_COMMIT() asm volatile("cp.async.commit_group;" ::: "memory")
#define CP_WAIT1()  asm volatile("cp.async.wait_group 1;" ::: "memory")
#define CP_WAIT0()  asm volatile("cp.async.wait_group 0;" ::: "memory")

__device__ __forceinline__ unsigned pack_h2(float v0, float v1, unsigned& lo_out) {
    __half h0 = __float2half_rn(v0), h1 = __float2half_rn(v1);
    __half l0 = __float2half_rn(v0 - __half2float(h0));
    __half l1 = __float2half_rn(v1 - __half2float(h1));
    lo_out = (unsigned)__half_as_ushort(l0) | ((unsigned)__half_as_ushort(l1) << 16);
    return (unsigned)__half_as_ushort(h0) | ((unsigned)__half_as_ushort(h1) << 16);
}
__device__ __forceinline__ unsigned pack_h1(float v0, float v1) {
    return (unsigned)__half_as_ushort(__float2half_rn(v0))
         | ((unsigned)__half_as_ushort(__float2half_rn(v1)) << 16);
}
__device__ __forceinline__ float up16(unsigned w, int half) {
    return __half2float(__ushort_as_half((unsigned short)(half ? (w >> 16) : w)));
}
__device__ __forceinline__ float ftanh(float x) {
    const float cx = fminf(fmaxf(x, -15.f), 15.f);
    const float e = __expf(2.f * cx);
    return __fdividef(e - 1.f, e + 1.f);
}

struct P {
    const __half *Ah, *Al;          // A planes (Al only for 2-plane modes)
    const __half *Bf, *B2f;         // weight planes
    const float *G3;                // fp32 G3 (F2 epilogue mask)
    __half *mA;                     // masked-A plane out (F2)
    const __half *F3Ah, *F3Bf;
    float *C, *C2;
    const float *cbias, *w1t, *bias, *b3, *E1;
    const __half *h1h;
    __half *Oh, *Ol;
    float *y, *yacc, *ld, *psum;
    int stage;
    float t, cacc, cin, foldcoef;
};

// ============ small kernel: 128x64 tile, 2-plane A, BK=32, K=64 ============
// MODE 0: by<8 G3 / by>=8 E1 (fp32 C)          grid (32,16)
// MODE 1: by<8 F1 (tanh -> h1h); by==8 fold    grid (32,9)
template <int MODE>
__global__ void __launch_bounds__(256, 3) mma_k(P p) {
    extern __shared__ __align__(16) char dynsmem[];
    __half* sAh = (__half*)dynsmem;
    __half* sAl = sAh + 2 * AT;
    __half* sBh = sAl + 2 * AT;

    const int tid = threadIdx.x, lane = tid & 31, wid = tid >> 5;
    const int wm = wid & 3, wn = wid >> 2;
    const int m0 = blockIdx.x * 128, by = blockIdx.y;

    if (MODE == 1 && by == 8) {   // fold rider
        if (p.foldcoef != 0.f && tid < 128) {
            const int m = m0 + tid;
            float s = 0.f;
            #pragma unroll
            for (int c = 0; c < 8; c++) s += p.psum[c * Bb + m];
            p.ld[m] += p.foldcoef * s;
        }
        return;
    }

    const __half *Ah = p.Ah, *Al = p.Al, *Bfp;
    int n0;
    float* C0 = nullptr;
    if (MODE == 0) {
        if (by < 8) { Bfp = p.Bf; C0 = p.C; n0 = by * 64; }
        else        { Bfp = p.B2f; C0 = p.C2; n0 = (by - 8) * 64; }
    } else {
        Bfp = p.Bf; n0 = by * 64;
    }
    constexpr int K = 64, lda = 64, ldb = 64, NT = K / 32;

    auto issue = [&](int kt) {
        const int buf = kt & 1;
        const int k0 = kt * 32;
        #pragma unroll
        for (int c = tid; c < 1024; c += 256) {
            const int plane = c >> 9, cc = c & 511;
            const int row = cc >> 2, ku = cc & 3;
            cp16((plane ? sAl : sAh) + buf * AT + row * SAS + ku * 8,
                 (plane ? Al : Ah) + (size_t)(m0 + row) * lda + k0 + ku * 8);
        }
        {
            const int row = tid >> 2, ku = tid & 3;
            cp16(sBh + buf * BT + row * SAS + ku * 8,
                 Bfp + (size_t)(n0 + row) * ldb + k0 + ku * 8);
        }
        CP_COMMIT();
    };

    const int l7 = lane & 7;
    const int aro = l7 + ((lane >> 3) & 1) * 8;
    const int aco = (lane >> 4) * 8;
    const int bro = l7 + (lane >> 4) * 8;
    const int bco = ((lane >> 3) & 1) * 8;

    float acc[2][4][4] = {};

    auto compute = [&](int buf) {
        const uint32_t bAh = sptr(sAh + buf * AT);
        const uint32_t bAl = sptr(sAl + buf * AT);
        const uint32_t bBh = sptr(sBh + buf * BT);
        #pragma unroll
        for (int kk = 0; kk < 2; kk++) {
            uint32_t ah[2][4], al[2][4], bh[2][4];
            #pragma unroll
            for (int mt = 0; mt < 2; mt++) {
                const uint32_t off = ((wm * 32 + mt * 16 + aro) * SAS + kk * 16 + aco) * 2;
                ldm4(bAh + off, ah[mt][0], ah[mt][1], ah[mt][2], ah[mt][3]);
                ldm4(bAl + off, al[mt][0], al[mt][1], al[mt][2], al[mt][3]);
            }
            #pragma unroll
            for (int pn = 0; pn < 2; pn++) {
                const uint32_t off = ((wn * 32 + pn * 16 + bro) * SAS + kk * 16 + bco) * 2;
                ldm4(bBh + off, bh[pn][0], bh[pn][1], bh[pn][2], bh[pn][3]);
            }
            #pragma unroll
            for (int mt = 0; mt < 2; mt++)
                #pragma unroll
                for (int nt = 0; nt < 4; nt++) {
                    const uint32_t b0 = bh[nt >> 1][(nt & 1) * 2], b1 = bh[nt >> 1][(nt & 1) * 2 + 1];
                    mma_f16(acc[mt][nt], ah[mt], b0, b1);
                    mma_f16(acc[mt][nt], al[mt], b0, b1);
                }
        }
    };

    issue(0);
    for (int kt = 0; kt < NT; kt++) {
        if (kt + 1 < NT) { issue(kt + 1); CP_WAIT1(); } else { CP_WAIT0(); }
        __syncthreads();
        compute(kt & 1);
        __syncthreads();
    }

    const int g = lane >> 2, tt = lane & 3;
    #pragma unroll
    for (int mt = 0; mt < 2; mt++)
        #pragma unroll
        for (int nt = 0; nt < 4; nt++) {
            const int c = n0 + wn * 32 + nt * 8 + tt * 2;
            #pragma unroll
            for (int hr = 0; hr < 2; hr++) {
                const int r = m0 + wm * 32 + mt * 16 + g + hr * 8;
                float v0 = acc[mt][nt][hr * 2 + 0];
                float v1 = acc[mt][nt][hr * 2 + 1];
                const size_t off = (size_t)r * 512 + c;
                if (MODE == 0) {
                    *(float2*)&C0[off] = make_float2(v0, v1);
                } else {
                    const float2 cb = *(const float2*)&p.cbias[off];
                    const float2 wt = *(const float2*)&p.w1t[c];
                    v0 = ftanh(v0 + cb.x + p.t * wt.x);
                    v1 = ftanh(v1 + cb.y + p.t * wt.y);
                    ((unsigned*)p.Oh)[off >> 1] = pack_h1(v0, v1);
                }
            }
        }
}

// ============ big kernel: 128x64 tile, 1-plane A, BK=32, K=512, 3 bufs, 1 sync/tile ============
// MODE 2: F2 (tanh -> h2h + mA)                                  grid (32,8)
// MODE 3: by<8 B2 (A=mA, logdet dot) / by==8 F3 (A=h2h) + RK4    grid (32,9)
template <int MODE>
__global__ void __launch_bounds__(256, 3) big_k(P p) {
    extern __shared__ __align__(16) char dynsmem[];
    __half* sA = (__half*)dynsmem;          // 3 * AT
    __half* sB = sA + 3 * AT;               // 3 * BT
    float* red = (float*)(sB + 3 * BT);

    const int tid = threadIdx.x, lane = tid & 31, wid = tid >> 5;
    const int wm = wid & 3, wn = wid >> 2;
    const int m0 = blockIdx.x * 128, by = blockIdx.y;

    const bool isF3 = (MODE == 3 && by == 8);
    const int n0 = isF3 ? 0 : by * 64;
    const __half* Ap = (MODE == 2) ? p.Ah : (isF3 ? p.F3Ah : p.Ah);
    const __half* Bp = (MODE == 2) ? p.Bf : (isF3 ? p.F3Bf : p.Bf);
    constexpr int NT = 16;   // K=512 / BK=32

    auto issue = [&](int kt) {
        if (kt < NT) {
            const int buf = kt % 3;
            const int k0 = kt * 32;
            #pragma unroll
            for (int c = tid; c < 512; c += 256) {
                const int row = c >> 2, ku = c & 3;
                cp16(sA + buf * AT + row * SAS + ku * 8,
                     Ap + (size_t)(m0 + row) * 512 + k0 + ku * 8);
            }
            {
                const int row = tid >> 2, ku = tid & 3;
                cp16(sB + buf * BT + row * SAS + ku * 8,
                     Bp + (size_t)(n0 + row) * 512 + k0 + ku * 8);
            }
        }
        CP_COMMIT();
    };

    const int l7 = lane & 7;
    const int aro = l7 + ((lane >> 3) & 1) * 8;
    const int aco = (lane >> 4) * 8;
    const int bro = l7 + (lane >> 4) * 8;
    const int bco = ((lane >> 3) & 1) * 8;

    float acc[2][4][4] = {};

    auto compute = [&](int buf) {
        const uint32_t bA = sptr(sA + buf * AT);
        const uint32_t bB = sptr(sB + buf * BT);
        #pragma unroll
        for (int kk = 0; kk < 2; kk++) {
            uint32_t ah[2][4], bh[2][4];
            #pragma unroll
            for (int mt = 0; mt < 2; mt++) {
                const uint32_t off = ((wm * 32 + mt * 16 + aro) * SAS + kk * 16 + aco) * 2;
                ldm4(bA + off, ah[mt][0], ah[mt][1], ah[mt][2], ah[mt][3]);
            }
            #pragma unroll
            for (int pn = 0; pn < 2; pn++) {
                const uint32_t off = ((wn * 32 + pn * 16 + bro) * SAS + kk * 16 + bco) * 2;
                ldm4(bB + off, bh[pn][0], bh[pn][1], bh[pn][2], bh[pn][3]);
            }
            #pragma unroll
            for (int mt = 0; mt < 2; mt++)
                #pragma unroll
                for (int nt = 0; nt < 4; nt++)
                    mma_f16(acc[mt][nt], ah[mt],
                            bh[nt >> 1][(nt & 1) * 2], bh[nt >> 1][(nt & 1) * 2 + 1]);
        }
    };

    issue(0);
    issue(1);
    for (int kt = 0; kt < NT; kt++) {
        CP_WAIT1();
        __syncthreads();
        issue(kt + 2);
        compute(kt % 3);
    }

    // ---- epilogues ----
    const int g = lane >> 2, tt = lane & 3;

    if (MODE == 2) {   // tanh -> h2h + mA
        #pragma unroll
        for (int mt = 0; mt < 2; mt++)
            #pragma unroll
            for (int nt = 0; nt < 4; nt++) {
                const int c = n0 + wn * 32 + nt * 8 + tt * 2;
                const float2 bi = *(const float2*)&p.bias[c];
                #pragma unroll
                for (int hr = 0; hr < 2; hr++) {
                    const int r = m0 + wm * 32 + mt * 16 + g + hr * 8;
                    const size_t off = (size_t)r * 512 + c;
                    const float v0 = ftanh(acc[mt][nt][hr * 2 + 0] + bi.x);
                    const float v1 = ftanh(acc[mt][nt][hr * 2 + 1] + bi.y);
                    ((unsigned*)p.Oh)[off >> 1] = pack_h1(v0, v1);
                    const float2 gv = *(const float2*)&p.G3[off];
                    ((unsigned*)p.mA)[off >> 1] =
                        pack_h1(gv.x * (1.f - v0 * v0), gv.y * (1.f - v1 * v1));
                }
            }
        return;
    }

    if (!isF3) {   // B2 logdet dot
        float s[4] = {0.f, 0.f, 0.f, 0.f};
        #pragma unroll
        for (int mt = 0; mt < 2; mt++)
            #pragma unroll
            for (int nt = 0; nt < 4; nt++) {
                const int c = n0 + wn * 32 + nt * 8 + tt * 2;
                #pragma unroll
                for (int hr = 0; hr < 2; hr++) {
                    const int r = m0 + wm * 32 + mt * 16 + g + hr * 8;
                    const size_t off = (size_t)r * 512 + c;
                    const unsigned hh = *(const unsigned*)&p.h1h[off];
                    const float2 e = *(const float2*)&p.E1[off];
                    const float h0 = up16(hh, 0), h1v = up16(hh, 1);
                    s[mt * 2 + hr] += acc[mt][nt][hr * 2 + 0] * (1.f - h0 * h0) * e.x
                                    + acc[mt][nt][hr * 2 + 1] * (1.f - h1v * h1v) * e.y;
                }
            }
        #pragma unroll
        for (int i = 0; i < 4; i++) {
            s[i] += __shfl_xor_sync(0xffffffffu, s[i], 1);
            s[i] += __shfl_xor_sync(0xffffffffu, s[i], 2);
        }
        if (tt == 0) {
            #pragma unroll
            for (int mt = 0; mt < 2; mt++)
                #pragma unroll
                for (int hr = 0; hr < 2; hr++)
                    red[(wm * 32 + mt * 16 + g + hr * 8) * 2 + wn] = s[mt * 2 + hr];
        }
        __syncthreads();
        if (tid < 128)
            p.psum[(size_t)by * Bb + m0 + tid] = red[tid * 2] + red[tid * 2 + 1];
        return;
    }

    // F3 + RK4 (yin kept as 2 planes)
    {
        unsigned* yinhU = (unsigned*)p.Oh;
        unsigned* yinlU = (unsigned*)p.Ol;
        #pragma unroll
        for (int mt = 0; mt < 2; mt++)
            #pragma unroll
            for (int nt = 0; nt < 4; nt++) {
                const int c = wn * 32 + nt * 8 + tt * 2;
                const float2 b3v = *(const float2*)&p.b3[c];
                #pragma unroll
                for (int hr = 0; hr < 2; hr++) {
                    const int r = m0 + wm * 32 + mt * 16 + g + hr * 8;
                    const size_t idx = (size_t)r * 64 + c;
                    const float kv0 = acc[mt][nt][hr * 2 + 0] + b3v.x;
                    const float kv1 = acc[mt][nt][hr * 2 + 1] + b3v.y;
                    const float2 base = (p.stage == 1) ? *(const float2*)&p.y[idx]
                                                       : *(const float2*)&p.yacc[idx];
                    const float ya0 = base.x + p.cacc * kv0;
                    const float ya1 = base.y + p.cacc * kv1;
                    float yi0, yi1;
                    if (p.stage == 4) {
                        *(float2*)&p.y[idx] = make_float2(ya0, ya1);
                        yi0 = ya0; yi1 = ya1;
                    } else {
                        *(float2*)&p.yacc[idx] = make_float2(ya0, ya1);
                        const float2 yv = *(const float2*)&p.y[idx];
                        yi0 = yv.x + p.cin * kv0;
                        yi1 = yv.y + p.cin * kv1;
                    }
                    unsigned lo, hi = pack_h2(yi0, yi1, lo);
                    yinhU[idx >> 1] = hi;
                    yinlU[idx >> 1] = lo;
                }
            }
    }
}

// ---------------- aux kernels ----------------
__device__ __forceinline__ void hsplit(float v, __half* h, __half* l, size_t i) {
    const __half hv = __float2half_rn(v);
    h[i] = hv;
    l[i] = __float2half_rn(v - __half2float(hv));
}
__global__ void prep_k(const float* __restrict__ eps, const float* __restrict__ W2,
                       const float* __restrict__ W3, const float* __restrict__ W1,
                       __half* eph, __half* epl,
                       __half* w2f, __half* w3f,
                       __half* w2tf, __half* w1ytf, __half* w3tf) {
    int i = blockIdx.x * 256 + threadIdx.x;
    if (i < Bb * Dd) { hsplit(eps[i], eph, epl, i); return; }
    i -= Bb * Dd;
    if (i < Hh * Hh) { w2f[i] = __float2half_rn(W2[i]); return; }
    i -= Hh * Hh;
    if (i < Hh * Dd) { w3f[i] = __float2half_rn(W3[i]); return; }
    i -= Hh * Dd;
    if (i < Hh * Hh) {
        const int r = i / Hh, c = i % Hh;
        w2tf[(size_t)c * Hh + r] = __float2half_rn(W2[i]);
        return;
    }
    i -= Hh * Hh;
    if (i < Dd * Hh) {
        const int r = i / Hh, c = i % Hh;
        w1ytf[(size_t)c * Dd + r] = __float2half_rn(W1[i]);
        return;
    }
    i -= Dd * Hh;
    if (i < Hh * Dd) {
        const int r = i / Dd, c = i % Dd;
        w3tf[(size_t)c * Hh + r] = __float2half_rn(W3[i]);
    }
}
__global__ void cbias_k(const float* __restrict__ cond, const float* __restrict__ W1c,
                        const float* __restrict__ b1, float* __restrict__ cb) {
    const int m = blockIdx.x;
    const int n = threadIdx.x * 4;
    float4 acc = *(const float4*)(b1 + n);
    #pragma unroll
    for (int k = 0; k < Cc; k++) {
        const float c = cond[m * Cc + k];
        const float4 w = *(const float4*)(W1c + (size_t)k * Hh + n);
        acc.x = fmaf(c, w.x, acc.x); acc.y = fmaf(c, w.y, acc.y);
        acc.z = fmaf(c, w.z, acc.z); acc.w = fmaf(c, w.w, acc.w);
    }
    *(float4*)(cb + (size_t)m * Hh + n) = acc;
}
__global__ void init_k(const float* __restrict__ x, float* __restrict__ y,
                       __half* __restrict__ yinh, __half* __restrict__ yinl,
                       float* __restrict__ ld) {
    const int i = blockIdx.x * blockDim.x + threadIdx.x;
    if (i < Bb * Dd) {
        const float v = x[i];
        y[i] = v;
        hsplit(v, yinh, yinl, i);
    }
    if (i < Bb) ld[i] = 0.f;
}
__global__ void out_k(const float* __restrict__ y, const float* __restrict__ ld,
                      const float* __restrict__ psum, float coef, float* __restrict__ out) {
    const int i = blockIdx.x * blockDim.x + threadIdx.x;
    if (i >= Bb * (Dd + 1)) return;
    const int m = i / (Dd + 1), c = i % (Dd + 1);
    if (c < Dd) {
        out[i] = y[(size_t)m * Dd + c];
    } else {
        float s = 0.f;
        #pragma unroll
        for (int c2 = 0; c2 < 8; c2++) s += psum[c2 * Bb + m];
        out[i] = ld[m] + coef * s;
    }
}

// ---------------- host ----------------
extern "C" void kernel_launch(void* const* d_in, const int* in_sizes, int n_in,
                              void* d_out, int out_size) {
    const float* x    = (const float*)d_in[0];
    const float* cond = (const float*)d_in[1];
    const float* eps  = (const float*)d_in[2];
    const float* W1   = (const float*)d_in[3];
    const float* b1   = (const float*)d_in[4];
    const float* W2   = (const float*)d_in[5];
    const float* b2   = (const float*)d_in[6];
    const float* W3   = (const float*)d_in[7];
    const float* b3   = (const float*)d_in[8];
    float* out = (float*)d_out;

    cudaFuncSetAttribute(mma_k<0>, cudaFuncAttributeMaxDynamicSharedMemorySize, SMEM_SM);
    cudaFuncSetAttribute(mma_k<1>, cudaFuncAttributeMaxDynamicSharedMemorySize, SMEM_SM);
    cudaFuncSetAttribute(big_k<2>, cudaFuncAttributeMaxDynamicSharedMemorySize, SMEM_BIG);
    cudaFuncSetAttribute(big_k<3>, cudaFuncAttributeMaxDynamicSharedMemorySize, SMEM_BIG);

    #define SYM(T, v, s) T* v; { void* _p; cudaGetSymbolAddress(&_p, s); v = (T*)_p; }
    SYM(float, y, g_y) SYM(float, yacc, g_yacc) SYM(float, cb, g_cb)
    SYM(float, G3, g_G3) SYM(float, E1, g_E1) SYM(float, ld, g_ld) SYM(float, psum, g_psum)
    SYM(__half, h1h, g_h1h) SYM(__half, h2h, g_h2h) SYM(__half, mAh, g_mAh)
    SYM(__half, yinh, g_yinh) SYM(__half, yinl, g_yinl)
    SYM(__half, epsh, g_epsh) SYM(__half, epsl, g_epsl)
    SYM(__half, W2f, g_W2f) SYM(__half, W2Tf, g_W2Tf)
    SYM(__half, W3f, g_W3f) SYM(__half, W3Tf, g_W3Tf)
    SYM(__half, W1yTf, g_W1yTf)
    #undef SYM

    init_k<<<(Bb * Dd + 255) / 256, 256>>>(x, y, yinh, yinl, ld);

    constexpr int PREP_N = Bb * Dd + 2 * Hh * Hh + 3 * Hh * Dd;
    const float dt = 1.0f / NS;
    float prev_cl = 0.f;

    for (int ib = 0; ib < NB; ib++) {
        const float* W1b  = W1 + (size_t)ib * (Dd + Cc + 1) * Hh;
        const float* b1b  = b1 + (size_t)ib * Hh;
        const float* W2b  = W2 + (size_t)ib * Hh * Hh;
        const float* b2b  = b2 + (size_t)ib * Hh;
        const float* W3b  = W3 + (size_t)ib * Hh * Dd;
        const float* b3b  = b3 + (size_t)ib * Dd;
        const float* epsb = eps + (size_t)ib * Bb * Dd;
        float* cbb = cb + (size_t)ib * Bb * Hh;
        float* G3b = G3 + (size_t)ib * Bb * Hh;
        float* E1b = E1 + (size_t)ib * Bb * Hh;
        __half *eph = epsh + (size_t)ib * Bb * Dd, *epl = epsl + (size_t)ib * Bb * Dd;
        __half* w2f  = W2f  + (size_t)ib * Hh * Hh;
        __half* w2tf = W2Tf + (size_t)ib * Hh * Hh;
        __half* w3f  = W3f  + (size_t)ib * Hh * Dd;
        __half* w3tf = W3Tf + (size_t)ib * Dd * Hh;
        __half* w1ytf = W1yTf + (size_t)ib * Hh * Dd;

        prep_k<<<(PREP_N + 255) / 256, 256>>>(epsb, W2b, W3b, W1b,
            eph, epl, w2f, w3f, w2tf, w1ytf, w3tf);
        cbias_k<<<Bb, 128>>>(cond, W1b + (size_t)Dd * Hh, b1b, cbb);

        {   // merged G3 (by<8) + E1 (by>=8)
            P p{}; p.Ah = eph; p.Al = epl;
            p.Bf = w3f; p.C = G3b;
            p.B2f = w1ytf; p.C2 = E1b;
            mma_k<0><<<dim3(32, 16), 256, SMEM_SM>>>(p);
        }

        for (int is = 0; is < NS; is++) {
            const float tbase = is * dt;
            for (int st = 1; st <= 4; st++) {
                const float t = tbase + (st == 1 ? 0.f : (st == 4 ? dt : 0.5f * dt));
                const float cacc = (st == 1 || st == 4) ? dt / 6.f : dt / 3.f;
                const float cin  = (st == 3) ? dt : 0.5f * dt;

                {   // F1 + fold rider
                    P p{}; p.Ah = yinh; p.Al = yinl; p.Bf = w1ytf;
                    p.cbias = cbb; p.w1t = W1b + (size_t)(Dd + Cc) * Hh; p.t = t;
                    p.Oh = h1h;
                    p.foldcoef = prev_cl; p.ld = ld; p.psum = psum;
                    mma_k<1><<<dim3(32, 9), 256, SMEM_SM>>>(p);
                }
                {   // F2: tanh -> h2h + mA
                    P p{}; p.Ah = h1h; p.Bf = w2tf;
                    p.bias = b2b; p.Oh = h2h; p.G3 = G3b; p.mA = mAh;
                    big_k<2><<<dim3(32, 8), 256, SMEM_BIG>>>(p);
                }
                {   // FUSED: B2 (A=mA) + logdet dot (by<8), F3 + RK4 (by==8)
                    P p{};
                    p.Ah = mAh; p.Bf = w2f;
                    p.F3Ah = h2h; p.F3Bf = w3tf;
                    p.h1h = h1h; p.E1 = E1b; p.psum = psum;
                    p.b3 = b3b; p.y = y; p.yacc = yacc; p.Oh = yinh; p.Ol = yinl;
                    p.stage = st; p.cacc = cacc; p.cin = cin;
                    big_k<3><<<dim3(32, 9), 256, SMEM_BIG>>>(p);
                }
                prev_cl = cacc;
            }
        }
    }

    out_k<<<(Bb * (Dd + 1) + 255) / 256, 256>>>(y, ld, psum, prev_cl, out);
}

// round 14
// speedup vs baseline: 2.1051x; 1.0559x over previous
#include <cuda_runtime.h>
#include <cuda_fp16.h>
#include <math.h>
#include <stdint.h>

namespace {
constexpr int Bb = 4096, Dd = 64, Cc = 16, Hh = 512, NB = 2, NS = 8;
constexpr int SAS = 40;               // smem row stride in halves (80B)
constexpr int AT = 128 * SAS;         // A halves per buffer
constexpr int BT = 64 * SAS;          // B halves per buffer
constexpr int SMEM_SM  = (2 * AT + 2 * AT + 2 * BT) * 2 + 1024;   // prologue (2-plane A, 2 bufs)
constexpr int SMEM_BIG = (3 * (AT + BT)) * 2 + 1024;              // 1-plane A, 3 bufs
}

// ---------------- device scratch (ping-pong where B2 overlaps) ----------------
__device__ __align__(16) __half g_h1h[2][Bb * Hh];
__device__ __align__(16) __half g_h2h[Bb * Hh];
__device__ __align__(16) __half g_mAh[2][Bb * Hh];
__device__ __align__(16) __half g_yinh[Bb * Dd];
__device__ __align__(16) float g_y[Bb * Dd], g_yacc[Bb * Dd];
__device__ __align__(16) float g_cb[NB * Bb * Hh], g_G3[NB * Bb * Hh], g_E1[NB * Bb * Hh];
__device__ __align__(16) float g_ld[Bb], g_psum[2][8 * Bb];
__device__ __align__(16) __half g_epsh[NB * Bb * Dd], g_epsl[NB * Bb * Dd];
__device__ __align__(16) __half g_W2f  [NB * Hh * Hh];   // [n][k] B2
__device__ __align__(16) __half g_W2Tf [NB * Hh * Hh];   // [n][k] F2
__device__ __align__(16) __half g_W3f  [NB * Hh * Dd];   // [512][64] G3
__device__ __align__(16) __half g_W3Tf [NB * Dd * Hh];   // [64][512] F3
__device__ __align__(16) __half g_W1yTf[NB * Hh * Dd];   // [512][64] F1/E1

// ---------------- helpers ----------------
__device__ __forceinline__ uint32_t sptr(const void* p) {
    return (uint32_t)__cvta_generic_to_shared(p);
}
__device__ __forceinline__ void ldm4(uint32_t a, uint32_t& r0, uint32_t& r1,
                                     uint32_t& r2, uint32_t& r3) {
    asm volatile("ldmatrix.sync.aligned.m8n8.x4.shared.b16 {%0,%1,%2,%3}, [%4];"
                 : "=r"(r0), "=r"(r1), "=r"(r2), "=r"(r3) : "r"(a));
}
__device__ __forceinline__ void mma_f16(float* c, const uint32_t* a, uint32_t b0, uint32_t b1) {
    asm volatile("mma.sync.aligned.m16n8k16.row.col.f32.f16.f16.f32 "
                 "{%0,%1,%2,%3}, {%4,%5,%6,%7}, {%8,%9}, {%0,%1,%2,%3};"
                 : "+f"(c[0]), "+f"(c[1]), "+f"(c[2]), "+f"(c[3])
                 : "r"(a[0]), "r"(a[1]), "r"(a[2]), "r"(a[3]), "r"(b0), "r"(b1));
}
__device__ __forceinline__ void cp16(void* dst, const void* src) {
    asm volatile("cp.async.cg.shared.global [%0], [%1], 16;"
                 :: "r"(sptr(dst)), "l"(src));
}
#define CP_COMMIT() asm volatile("cp.async.commit_group;" ::: "memory")
#define CP_WAIT1()  asm volatile("cp.async.wait_group 1;" ::: "memory")
#define CP_WAIT0()  asm volatile("cp.async.wait_group 0;" ::: "memory")

__device__ __forceinline__ unsigned pack_h1(float v0, float v1) {
    return (unsigned)__half_as_ushort(__float2half_rn(v0))
         | ((unsigned)__half_as_ushort(__float2half_rn(v1)) << 16);
}
__device__ __forceinline__ float up16(unsigned w, int half) {
    return __half2float(__ushort_as_half((unsigned short)(half ? (w >> 16) : w)));
}
__device__ __forceinline__ float ftanh(float x) {
    const float cx = fminf(fmaxf(x, -15.f), 15.f);
    const float e = __expf(2.f * cx);
    return __fdividef(e - 1.f, e + 1.f);
}

struct P {
    const __half *A, *Al;           // A planes (Al only for prologue)
    const __half *B, *B2f;          // weight planes
    const float *G3;                // fp32 G3 (F2 epilogue mask)
    __half *mA;
    float *C, *C2;
    const float *cbias, *w1t, *bias, *b3, *E1;
    const __half *h1;               // for B2 logdet dot
    __half *Oh;                     // h1/h2/yin output plane
    float *y, *yacc, *ld, *psum;
    const float *psumPrev;
    int stage;
    float t, cacc, cin, foldcoef;
};

// ============ prologue kernel: 128x64 tile, 2-plane A (eps), K=64 ============
// by<8 G3 / by>=8 E1 (fp32 C)   grid (32,16)
__global__ void __launch_bounds__(256, 3) pro_k(P p) {
    extern __shared__ __align__(16) char dynsmem[];
    __half* sAh = (__half*)dynsmem;
    __half* sAl = sAh + 2 * AT;
    __half* sBh = sAl + 2 * AT;

    const int tid = threadIdx.x, lane = tid & 31, wid = tid >> 5;
    const int wm = wid & 3, wn = wid >> 2;
    const int m0 = blockIdx.x * 128, by = blockIdx.y;

    const __half *Ah = p.A, *Al = p.Al, *Bfp;
    int n0;
    float* C0;
    if (by < 8) { Bfp = p.B; C0 = p.C; n0 = by * 64; }
    else        { Bfp = p.B2f; C0 = p.C2; n0 = (by - 8) * 64; }
    constexpr int NT = 2;

    auto issue = [&](int kt) {
        const int buf = kt & 1;
        const int k0 = kt * 32;
        #pragma unroll
        for (int c = tid; c < 1024; c += 256) {
            const int plane = c >> 9, cc = c & 511;
            const int row = cc >> 2, ku = cc & 3;
            cp16((plane ? sAl : sAh) + buf * AT + row * SAS + ku * 8,
                 (plane ? Al : Ah) + (size_t)(m0 + row) * 64 + k0 + ku * 8);
        }
        {
            const int row = tid >> 2, ku = tid & 3;
            cp16(sBh + buf * BT + row * SAS + ku * 8,
                 Bfp + (size_t)(n0 + row) * 64 + k0 + ku * 8);
        }
        CP_COMMIT();
    };

    const int l7 = lane & 7;
    const int aro = l7 + ((lane >> 3) & 1) * 8;
    const int aco = (lane >> 4) * 8;
    const int bro = l7 + (lane >> 4) * 8;
    const int bco = ((lane >> 3) & 1) * 8;

    float acc[2][4][4] = {};

    auto compute = [&](int buf) {
        const uint32_t bAh = sptr(sAh + buf * AT);
        const uint32_t bAl = sptr(sAl + buf * AT);
        const uint32_t bBh = sptr(sBh + buf * BT);
        #pragma unroll
        for (int kk = 0; kk < 2; kk++) {
            uint32_t ah[2][4], al[2][4], bh[2][4];
            #pragma unroll
            for (int mt = 0; mt < 2; mt++) {
                const uint32_t off = ((wm * 32 + mt * 16 + aro) * SAS + kk * 16 + aco) * 2;
                ldm4(bAh + off, ah[mt][0], ah[mt][1], ah[mt][2], ah[mt][3]);
                ldm4(bAl + off, al[mt][0], al[mt][1], al[mt][2], al[mt][3]);
            }
            #pragma unroll
            for (int pn = 0; pn < 2; pn++) {
                const uint32_t off = ((wn * 32 + pn * 16 + bro) * SAS + kk * 16 + bco) * 2;
                ldm4(bBh + off, bh[pn][0], bh[pn][1], bh[pn][2], bh[pn][3]);
            }
            #pragma unroll
            for (int mt = 0; mt < 2; mt++)
                #pragma unroll
                for (int nt = 0; nt < 4; nt++) {
                    const uint32_t b0 = bh[nt >> 1][(nt & 1) * 2], b1 = bh[nt >> 1][(nt & 1) * 2 + 1];
                    mma_f16(acc[mt][nt], ah[mt], b0, b1);
                    mma_f16(acc[mt][nt], al[mt], b0, b1);
                }
        }
    };

    issue(0);
    for (int kt = 0; kt < NT; kt++) {
        if (kt + 1 < NT) { issue(kt + 1); CP_WAIT1(); } else { CP_WAIT0(); }
        __syncthreads();
        compute(kt & 1);
        __syncthreads();
    }

    const int g = lane >> 2, tt = lane & 3;
    #pragma unroll
    for (int mt = 0; mt < 2; mt++)
        #pragma unroll
        for (int nt = 0; nt < 4; nt++) {
            const int c = n0 + wn * 32 + nt * 8 + tt * 2;
            #pragma unroll
            for (int hr = 0; hr < 2; hr++) {
                const int r = m0 + wm * 32 + mt * 16 + g + hr * 8;
                *(float2*)&C0[(size_t)r * 512 + c] =
                    make_float2(acc[mt][nt][hr * 2 + 0], acc[mt][nt][hr * 2 + 1]);
            }
        }
}

// ============ big kernel: 128x64 tile, 1-plane A, BK=32, 3 bufs, 1 sync/tile ============
// MODE 1: F1 (K=64, tanh+cbias+t*w1t -> h1[q])      grid (32,8)
// MODE 2: F2 (K=512, tanh -> h2 + mA[q])            grid (32,8)
// MODE 3: by<8 B2 (K=512, A=mA[q], logdet->psum[q]); by==8 fold psumPrev   grid (32,9)
// MODE 4: F3 (K=512, A=h2, RK4 -> y/yacc/yin)       grid (32,1)
template <int MODE>
__global__ void __launch_bounds__(256, 3) big_k(P p) {
    extern __shared__ __align__(16) char dynsmem[];
    __half* sA = (__half*)dynsmem;          // 3 * AT
    __half* sB = sA + 3 * AT;               // 3 * BT
    float* red = (float*)(sB + 3 * BT);

    const int tid = threadIdx.x, lane = tid & 31, wid = tid >> 5;
    const int wm = wid & 3, wn = wid >> 2;
    const int m0 = blockIdx.x * 128, by = blockIdx.y;

    if (MODE == 3 && by == 8) {   // fold rider (previous stage's psum)
        if (p.foldcoef != 0.f && tid < 128) {
            const int m = m0 + tid;
            float s = 0.f;
            #pragma unroll
            for (int c = 0; c < 8; c++) s += p.psumPrev[c * Bb + m];
            p.ld[m] += p.foldcoef * s;
        }
        return;
    }

    const int K   = (MODE == 1) ? 64 : 512;
    const int lda = (MODE == 1) ? 64 : 512;
    const int ldb = (MODE == 1) ? 64 : 512;
    const int n0  = (MODE == 4) ? 0 : by * 64;
    const __half* Ap = p.A;
    const __half* Bp = p.B;
    const int NT = K / 32;

    auto issue = [&](int kt) {
        if (kt < NT) {
            const int buf = kt % 3;
            const int k0 = kt * 32;
            #pragma unroll
            for (int c = tid; c < 512; c += 256) {
                const int row = c >> 2, ku = c & 3;
                cp16(sA + buf * AT + row * SAS + ku * 8,
                     Ap + (size_t)(m0 + row) * lda + k0 + ku * 8);
            }
            {
                const int row = tid >> 2, ku = tid & 3;
                cp16(sB + buf * BT + row * SAS + ku * 8,
                     Bp + (size_t)(n0 + row) * ldb + k0 + ku * 8);
            }
        }
        CP_COMMIT();
    };

    const int l7 = lane & 7;
    const int aro = l7 + ((lane >> 3) & 1) * 8;
    const int aco = (lane >> 4) * 8;
    const int bro = l7 + (lane >> 4) * 8;
    const int bco = ((lane >> 3) & 1) * 8;

    float acc[2][4][4] = {};

    auto compute = [&](int buf) {
        const uint32_t bA = sptr(sA + buf * AT);
        const uint32_t bB = sptr(sB + buf * BT);
        #pragma unroll
        for (int kk = 0; kk < 2; kk++) {
            uint32_t ah[2][4], bh[2][4];
            #pragma unroll
            for (int mt = 0; mt < 2; mt++) {
                const uint32_t off = ((wm * 32 + mt * 16 + aro) * SAS + kk * 16 + aco) * 2;
                ldm4(bA + off, ah[mt][0], ah[mt][1], ah[mt][2], ah[mt][3]);
            }
            #pragma unroll
            for (int pn = 0; pn < 2; pn++) {
                const uint32_t off = ((wn * 32 + pn * 16 + bro) * SAS + kk * 16 + bco) * 2;
                ldm4(bB + off, bh[pn][0], bh[pn][1], bh[pn][2], bh[pn][3]);
            }
            #pragma unroll
            for (int mt = 0; mt < 2; mt++)
                #pragma unroll
                for (int nt = 0; nt < 4; nt++)
                    mma_f16(acc[mt][nt], ah[mt],
                            bh[nt >> 1][(nt & 1) * 2], bh[nt >> 1][(nt & 1) * 2 + 1]);
        }
    };

    issue(0);
    issue(1);
    for (int kt = 0; kt < NT; kt++) {
        CP_WAIT1();
        __syncthreads();
        issue(kt + 2);
        compute(kt % 3);
    }

    // ---- epilogues ----
    const int g = lane >> 2, tt = lane & 3;

    if (MODE == 1) {   // F1: tanh(v + cbias + t*w1t) -> h1 plane
        #pragma unroll
        for (int mt = 0; mt < 2; mt++)
            #pragma unroll
            for (int nt = 0; nt < 4; nt++) {
                const int c = n0 + wn * 32 + nt * 8 + tt * 2;
                const float2 wt = *(const float2*)&p.w1t[c];
                #pragma unroll
                for (int hr = 0; hr < 2; hr++) {
                    const int r = m0 + wm * 32 + mt * 16 + g + hr * 8;
                    const size_t off = (size_t)r * 512 + c;
                    const float2 cb = *(const float2*)&p.cbias[off];
                    const float v0 = ftanh(acc[mt][nt][hr * 2 + 0] + cb.x + p.t * wt.x);
                    const float v1 = ftanh(acc[mt][nt][hr * 2 + 1] + cb.y + p.t * wt.y);
                    ((unsigned*)p.Oh)[off >> 1] = pack_h1(v0, v1);
                }
            }
        return;
    }

    if (MODE == 2) {   // F2: tanh -> h2 + mA
        #pragma unroll
        for (int mt = 0; mt < 2; mt++)
            #pragma unroll
            for (int nt = 0; nt < 4; nt++) {
                const int c = n0 + wn * 32 + nt * 8 + tt * 2;
                const float2 bi = *(const float2*)&p.bias[c];
                #pragma unroll
                for (int hr = 0; hr < 2; hr++) {
                    const int r = m0 + wm * 32 + mt * 16 + g + hr * 8;
                    const size_t off = (size_t)r * 512 + c;
                    const float v0 = ftanh(acc[mt][nt][hr * 2 + 0] + bi.x);
                    const float v1 = ftanh(acc[mt][nt][hr * 2 + 1] + bi.y);
                    ((unsigned*)p.Oh)[off >> 1] = pack_h1(v0, v1);
                    const float2 gv = *(const float2*)&p.G3[off];
                    ((unsigned*)p.mA)[off >> 1] =
                        pack_h1(gv.x * (1.f - v0 * v0), gv.y * (1.f - v1 * v1));
                }
            }
        return;
    }

    if (MODE == 3) {   // B2 logdet dot
        float s[4] = {0.f, 0.f, 0.f, 0.f};
        #pragma unroll
        for (int mt = 0; mt < 2; mt++)
            #pragma unroll
            for (int nt = 0; nt < 4; nt++) {
                const int c = n0 + wn * 32 + nt * 8 + tt * 2;
                #pragma unroll
                for (int hr = 0; hr < 2; hr++) {
                    const int r = m0 + wm * 32 + mt * 16 + g + hr * 8;
                    const size_t off = (size_t)r * 512 + c;
                    const unsigned hh = *(const unsigned*)&p.h1[off];
                    const float2 e = *(const float2*)&p.E1[off];
                    const float h0 = up16(hh, 0), h1v = up16(hh, 1);
                    s[mt * 2 + hr] += acc[mt][nt][hr * 2 + 0] * (1.f - h0 * h0) * e.x
                                    + acc[mt][nt][hr * 2 + 1] * (1.f - h1v * h1v) * e.y;
                }
            }
        #pragma unroll
        for (int i = 0; i < 4; i++) {
            s[i] += __shfl_xor_sync(0xffffffffu, s[i], 1);
            s[i] += __shfl_xor_sync(0xffffffffu, s[i], 2);
        }
        if (tt == 0) {
            #pragma unroll
            for (int mt = 0; mt < 2; mt++)
                #pragma unroll
                for (int hr = 0; hr < 2; hr++)
                    red[(wm * 32 + mt * 16 + g + hr * 8) * 2 + wn] = s[mt * 2 + hr];
        }
        __syncthreads();
        if (tid < 128)
            p.psum[(size_t)by * Bb + m0 + tid] = red[tid * 2] + red[tid * 2 + 1];
        return;
    }

    // MODE 4: F3 + RK4 (yin single plane)
    {
        #pragma unroll
        for (int mt = 0; mt < 2; mt++)
            #pragma unroll
            for (int nt = 0; nt < 4; nt++) {
                const int c = wn * 32 + nt * 8 + tt * 2;
                const float2 b3v = *(const float2*)&p.b3[c];
                #pragma unroll
                for (int hr = 0; hr < 2; hr++) {
                    const int r = m0 + wm * 32 + mt * 16 + g + hr * 8;
                    const size_t idx = (size_t)r * 64 + c;
                    const float kv0 = acc[mt][nt][hr * 2 + 0] + b3v.x;
                    const float kv1 = acc[mt][nt][hr * 2 + 1] + b3v.y;
                    const float2 base = (p.stage == 1) ? *(const float2*)&p.y[idx]
                                                       : *(const float2*)&p.yacc[idx];
                    const float ya0 = base.x + p.cacc * kv0;
                    const float ya1 = base.y + p.cacc * kv1;
                    float yi0, yi1;
                    if (p.stage == 4) {
                        *(float2*)&p.y[idx] = make_float2(ya0, ya1);
                        yi0 = ya0; yi1 = ya1;
                    } else {
                        *(float2*)&p.yacc[idx] = make_float2(ya0, ya1);
                        const float2 yv = *(const float2*)&p.y[idx];
                        yi0 = yv.x + p.cin * kv0;
                        yi1 = yv.y + p.cin * kv1;
                    }
                    ((unsigned*)p.Oh)[idx >> 1] = pack_h1(yi0, yi1);
                }
            }
    }
}

// ---------------- aux kernels ----------------
__device__ __forceinline__ void hsplit(float v, __half* h, __half* l, size_t i) {
    const __half hv = __float2half_rn(v);
    h[i] = hv;
    l[i] = __float2half_rn(v - __half2float(hv));
}
__global__ void prep_k(const float* __restrict__ eps, const float* __restrict__ W2,
                       const float* __restrict__ W3, const float* __restrict__ W1,
                       __half* eph, __half* epl,
                       __half* w2f, __half* w3f,
                       __half* w2tf, __half* w1ytf, __half* w3tf) {
    int i = blockIdx.x * 256 + threadIdx.x;
    if (i < Bb * Dd) { hsplit(eps[i], eph, epl, i); return; }
    i -= Bb * Dd;
    if (i < Hh * Hh) { w2f[i] = __float2half_rn(W2[i]); return; }
    i -= Hh * Hh;
    if (i < Hh * Dd) { w3f[i] = __float2half_rn(W3[i]); return; }
    i -= Hh * Dd;
    if (i < Hh * Hh) {
        const int r = i / Hh, c = i % Hh;
        w2tf[(size_t)c * Hh + r] = __float2half_rn(W2[i]);
        return;
    }
    i -= Hh * Hh;
    if (i < Dd * Hh) {
        const int r = i / Hh, c = i % Hh;
        w1ytf[(size_t)c * Dd + r] = __float2half_rn(W1[i]);
        return;
    }
    i -= Dd * Hh;
    if (i < Hh * Dd) {
        const int r = i / Dd, c = i % Dd;
        w3tf[(size_t)c * Hh + r] = __float2half_rn(W3[i]);
    }
}
__global__ void cbias_k(const float* __restrict__ cond, const float* __restrict__ W1c,
                        const float* __restrict__ b1, float* __restrict__ cb) {
    const int m = blockIdx.x;
    const int n = threadIdx.x * 4;
    float4 acc = *(const float4*)(b1 + n);
    #pragma unroll
    for (int k = 0; k < Cc; k++) {
        const float c = cond[m * Cc + k];
        const float4 w = *(const float4*)(W1c + (size_t)k * Hh + n);
        acc.x = fmaf(c, w.x, acc.x); acc.y = fmaf(c, w.y, acc.y);
        acc.z = fmaf(c, w.z, acc.z); acc.w = fmaf(c, w.w, acc.w);
    }
    *(float4*)(cb + (size_t)m * Hh + n) = acc;
}
__global__ void init_k(const float* __restrict__ x, float* __restrict__ y,
                       __half* __restrict__ yinh, float* __restrict__ ld) {
    const int i = blockIdx.x * blockDim.x + threadIdx.x;
    if (i < Bb * Dd) {
        const float v = x[i];
        y[i] = v;
        yinh[i] = __float2half_rn(v);
    }
    if (i < Bb) ld[i] = 0.f;
}
__global__ void out_k(const float* __restrict__ y, const float* __restrict__ ld,
                      const float* __restrict__ psum, float coef, float* __restrict__ out) {
    const int i = blockIdx.x * blockDim.x + threadIdx.x;
    if (i >= Bb * (Dd + 1)) return;
    const int m = i / (Dd + 1), c = i % (Dd + 1);
    if (c < Dd) {
        out[i] = y[(size_t)m * Dd + c];
    } else {
        float s = 0.f;
        #pragma unroll
        for (int c2 = 0; c2 < 8; c2++) s += psum[c2 * Bb + m];
        out[i] = ld[m] + coef * s;
    }
}

// ---------------- host ----------------
extern "C" void kernel_launch(void* const* d_in, const int* in_sizes, int n_in,
                              void* d_out, int out_size) {
    const float* x    = (const float*)d_in[0];
    const float* cond = (const float*)d_in[1];
    const float* eps  = (const float*)d_in[2];
    const float* W1   = (const float*)d_in[3];
    const float* b1   = (const float*)d_in[4];
    const float* W2   = (const float*)d_in[5];
    const float* b2   = (const float*)d_in[6];
    const float* W3   = (const float*)d_in[7];
    const float* b3   = (const float*)d_in[8];
    float* out = (float*)d_out;

    static cudaStream_t s2 = nullptr;
    static cudaEvent_t evF2 = nullptr, evB2a = nullptr, evB2b = nullptr;
    if (s2 == nullptr) {
        cudaStreamCreateWithFlags(&s2, cudaStreamNonBlocking);
        cudaEventCreateWithFlags(&evF2, cudaEventDisableTiming);
        cudaEventCreateWithFlags(&evB2a, cudaEventDisableTiming);
        cudaEventCreateWithFlags(&evB2b, cudaEventDisableTiming);
        cudaFuncSetAttribute(pro_k, cudaFuncAttributeMaxDynamicSharedMemorySize, SMEM_SM);
        cudaFuncSetAttribute(big_k<1>, cudaFuncAttributeMaxDynamicSharedMemorySize, SMEM_BIG);
        cudaFuncSetAttribute(big_k<2>, cudaFuncAttributeMaxDynamicSharedMemorySize, SMEM_BIG);
        cudaFuncSetAttribute(big_k<3>, cudaFuncAttributeMaxDynamicSharedMemorySize, SMEM_BIG);
        cudaFuncSetAttribute(big_k<4>, cudaFuncAttributeMaxDynamicSharedMemorySize, SMEM_BIG);
    }

    #define SYM(T, v, s) T* v; { void* _p; cudaGetSymbolAddress(&_p, s); v = (T*)_p; }
    SYM(float, y, g_y) SYM(float, yacc, g_yacc) SYM(float, cb, g_cb)
    SYM(float, G3, g_G3) SYM(float, E1, g_E1) SYM(float, ld, g_ld) SYM(float, psum, g_psum)
    SYM(__half, h1h, g_h1h) SYM(__half, h2h, g_h2h) SYM(__half, mAh, g_mAh)
    SYM(__half, yinh, g_yinh)
    SYM(__half, epsh, g_epsh) SYM(__half, epsl, g_epsl)
    SYM(__half, W2f, g_W2f) SYM(__half, W2Tf, g_W2Tf)
    SYM(__half, W3f, g_W3f) SYM(__half, W3Tf, g_W3Tf)
    SYM(__half, W1yTf, g_W1yTf)
    #undef SYM

    init_k<<<(Bb * Dd + 255) / 256, 256>>>(x, y, yinh, ld);

    constexpr int PREP_N = Bb * Dd + 2 * Hh * Hh + 3 * Hh * Dd;
    const float dt = 1.0f / NS;
    float prev_cl = 0.f;
    int gs = 0;

    for (int ib = 0; ib < NB; ib++) {
        const float* W1b  = W1 + (size_t)ib * (Dd + Cc + 1) * Hh;
        const float* b1b  = b1 + (size_t)ib * Hh;
        const float* W2b  = W2 + (size_t)ib * Hh * Hh;
        const float* b2b  = b2 + (size_t)ib * Hh;
        const float* W3b  = W3 + (size_t)ib * Hh * Dd;
        const float* b3b  = b3 + (size_t)ib * Dd;
        const float* epsb = eps + (size_t)ib * Bb * Dd;
        float* cbb = cb + (size_t)ib * Bb * Hh;
        float* G3b = G3 + (size_t)ib * Bb * Hh;
        float* E1b = E1 + (size_t)ib * Bb * Hh;
        __half *eph = epsh + (size_t)ib * Bb * Dd, *epl = epsl + (size_t)ib * Bb * Dd;
        __half* w2f  = W2f  + (size_t)ib * Hh * Hh;
        __half* w2tf = W2Tf + (size_t)ib * Hh * Hh;
        __half* w3f  = W3f  + (size_t)ib * Hh * Dd;
        __half* w3tf = W3Tf + (size_t)ib * Dd * Hh;
        __half* w1ytf = W1yTf + (size_t)ib * Hh * Dd;

        prep_k<<<(PREP_N + 255) / 256, 256>>>(epsb, W2b, W3b, W1b,
            eph, epl, w2f, w3f, w2tf, w1ytf, w3tf);
        cbias_k<<<Bb, 128>>>(cond, W1b + (size_t)Dd * Hh, b1b, cbb);

        {   // merged G3 (by<8) + E1 (by>=8)
            P p{}; p.A = eph; p.Al = epl;
            p.B = w3f; p.C = G3b;
            p.B2f = w1ytf; p.C2 = E1b;
            pro_k<<<dim3(32, 16), 256, SMEM_SM>>>(p);
        }

        for (int is = 0; is < NS; is++) {
            const float tbase = is * dt;
            for (int st = 1; st <= 4; st++) {
                const float t = tbase + (st == 1 ? 0.f : (st == 4 ? dt : 0.5f * dt));
                const float cacc = (st == 1 || st == 4) ? dt / 6.f : dt / 3.f;
                const float cin  = (st == 3) ? dt : 0.5f * dt;
                const int q = gs & 1;
                __half* h1q = h1h + (size_t)q * Bb * Hh;
                __half* mAq = mAh + (size_t)q * Bb * Hh;
                float* psq  = psum + (size_t)q * 8 * Bb;
                float* pspv = psum + (size_t)(q ^ 1) * 8 * Bb;
                cudaEvent_t evq = q ? evB2b : evB2a;

                if (gs >= 2) cudaStreamWaitEvent(0, evq, 0);   // B2(gs-2) done: h1[q]/mA[q] free

                {   // F1 -> h1[q]
                    P p{}; p.A = yinh; p.B = w1ytf;
                    p.cbias = cbb; p.w1t = W1b + (size_t)(Dd + Cc) * Hh; p.t = t;
                    p.Oh = h1q;
                    big_k<1><<<dim3(32, 8), 256, SMEM_BIG>>>(p);
                }
                {   // F2 -> h2 + mA[q]
                    P p{}; p.A = h1q; p.B = w2tf;
                    p.bias = b2b; p.Oh = h2h; p.G3 = G3b; p.mA = mAq;
                    big_k<2><<<dim3(32, 8), 256, SMEM_BIG>>>(p);
                }
                cudaEventRecord(evF2, 0);
                {   // F3 + RK4 (main)
                    P p{}; p.A = h2h; p.B = w3tf;
                    p.b3 = b3b; p.y = y; p.yacc = yacc; p.Oh = yinh;
                    p.stage = st; p.cacc = cacc; p.cin = cin;
                    big_k<4><<<dim3(32, 1), 256, SMEM_BIG>>>(p);
                }
                cudaStreamWaitEvent(s2, evF2, 0);
                {   // B2 (A=mA[q]) + logdet -> psum[q]; fold rider for psum[q^1] (stream 2)
                    P p{}; p.A = mAq; p.B = w2f;
                    p.h1 = h1q; p.E1 = E1b;
                    p.psum = psq; p.psumPrev = pspv;
                    p.ld = ld; p.foldcoef = prev_cl;
                    big_k<3><<<dim3(32, 9), 256, SMEM_BIG, s2>>>(p);
                }
                cudaEventRecord(evq, s2);

                prev_cl = cacc;
                gs++;
            }
        }
    }

    cudaStreamWaitEvent(0, evB2a, 0);
    cudaStreamWaitEvent(0, evB2b, 0);
    out_k<<<(Bb * (Dd + 1) + 255) / 256, 256>>>(
        y, ld, psum + (size_t)((gs - 1) & 1) * 8 * Bb, prev_cl, out);
}